// round 5
// baseline (speedup 1.0000x reference)
#include <cuda_runtime.h>

#define NN      30000
#define KNBR    20
#define DIM     128
#define M_TILE  32
#define N_TILES 938                  // ceil(30000/32)
#define GRID    296                  // 2 CTAs/SM * 148 SMs
#define NTHREADS 384                 // 8 consumer warps + 4 producer warps
#define AGG_STRIDE 388               // +4 pad: conflict-free a-loads
#define KK_TILE 32

// agg buffer: rows 0..30 padded (stride 388), row 31 trimmed to 384
#define AGGSZ  (31 * AGG_STRIDE + 384)   // 12412 floats
#define WS_OFF (2 * AGGSZ)               // 24824
#define SMEM_FLOATS (WS_OFF + KK_TILE * DIM)  // 28920
#define SMEM_BYTES (SMEM_FLOATS * 4)          // 115680 -> 2 CTAs/SM

// named barriers: 1,2 = full[buf]; 3,4 = empty[buf]; 5 = consumer-only
#define BAR_SYNC(id, cnt)  asm volatile("bar.sync %0, %1;"   :: "r"(id), "r"(cnt) : "memory")
#define BAR_ARRIVE(id, cnt) asm volatile("bar.arrive %0, %1;" :: "r"(id), "r"(cnt) : "memory")

typedef unsigned long long u64;

__device__ __forceinline__ u64 fma2(u64 a, u64 b, u64 c) {
    u64 d;
    asm("fma.rn.f32x2 %0, %1, %2, %3;" : "=l"(d) : "l"(a), "l"(b), "l"(c));
    return d;
}
__device__ __forceinline__ u64 add2(u64 a, u64 b) {
    u64 d;
    asm("add.rn.f32x2 %0, %1, %2;" : "=l"(d) : "l"(a), "l"(b));
    return d;
}
__device__ __forceinline__ u64 pack2(float x) {
    u64 d;
    unsigned r = __float_as_uint(x);
    asm("mov.b64 %0, {%1, %2};" : "=l"(d) : "r"(r), "r"(r));
    return d;
}
__device__ __forceinline__ u64 pack2b(float lo, float hi) {
    u64 d;
    asm("mov.b64 %0, {%1, %2};" : "=l"(d) : "r"(__float_as_uint(lo)), "r"(__float_as_uint(hi)));
    return d;
}
__device__ __forceinline__ void unpack2(u64 v, float& lo, float& hi) {
    unsigned a, b;
    asm("mov.b64 {%0, %1}, %2;" : "=r"(a), "=r"(b) : "l"(v));
    lo = __uint_as_float(a);
    hi = __uint_as_float(b);
}
__device__ __forceinline__ void unpack2i(u64 v, unsigned& lo, unsigned& hi) {
    asm("mov.b64 {%0, %1}, %2;" : "=r"(lo), "=r"(hi) : "l"(v));
}

// Packed 2-lane cos for x in [0, ~1.2e4]: Cody-Waite mod-pi reduction (q < 2^12
// so q*P1 exact), MUFU.COS on |r|<=pi/2, sign flip by parity of q.
__device__ __forceinline__ u64 cos2(u64 x2, u64 INVPI2, u64 MAGIC2, u64 NMAGIC2,
                                    u64 P1N2, u64 P2N2, u64 P3N2) {
    u64 qm2 = fma2(x2, INVPI2, MAGIC2);
    unsigned iq0, iq1;
    unpack2i(qm2, iq0, iq1);
    u64 q2 = add2(qm2, NMAGIC2);
    u64 r2 = fma2(q2, P1N2, x2);
    r2 = fma2(q2, P2N2, r2);
    r2 = fma2(q2, P3N2, r2);
    float rl, rh;
    unpack2(r2, rl, rh);
    unsigned ul = __float_as_uint(__cosf(rl)) ^ (iq0 << 31);
    unsigned uh = __float_as_uint(__cosf(rh)) ^ (iq1 << 31);
    u64 d;
    asm("mov.b64 %0, {%1, %2};" : "=l"(d) : "r"(ul), "r"(uh));
    return d;
}

// W slice prefetch: KK_TILE*DIM = 4096 floats = 1024 float4 / 256 consumers
__device__ __forceinline__ void ldW(const float* __restrict__ W, int slice, float4 r[4]) {
    const float4* p = (const float4*)(W + slice * KK_TILE * DIM);
#pragma unroll
    for (int j = 0; j < 4; ++j) r[j] = p[threadIdx.x + j * 256];
}
__device__ __forceinline__ void stW(float* Ws, const float4 r[4]) {
    float4* p = (float4*)Ws;
#pragma unroll
    for (int j = 0; j < 4; ++j) p[threadIdx.x + j * 256] = r[j];
}

// 32-deep slice: thread owns rows {r8+8i} and cols [coff, coff+4)
__device__ __forceinline__ void gemm_slice(const float* __restrict__ aS,
                                           const float* __restrict__ Ws,
                                           int r8, int coff,
                                           u64 (&acc)[4][2]) {
#pragma unroll
    for (int kk4 = 0; kk4 < KK_TILE / 4; ++kk4) {
        float a4[4][4];
#pragma unroll
        for (int i = 0; i < 4; ++i)
            *(float4*)a4[i] = *(const float4*)&aS[(r8 + 8 * i) * AGG_STRIDE + kk4 * 4];
        ulonglong2 bv[4];
#pragma unroll
        for (int k = 0; k < 4; ++k)
            bv[k] = *(const ulonglong2*)&Ws[(kk4 * 4 + k) * DIM + coff];
#pragma unroll
        for (int k = 0; k < 4; ++k)
#pragma unroll
            for (int i = 0; i < 4; ++i) {
                u64 aa = pack2(a4[i][k]);
                acc[i][0] = fma2(aa, bv[k].x, acc[i][0]);
                acc[i][1] = fma2(aa, bv[k].y, acc[i][1]);
            }
    }
}

__global__ void __launch_bounds__(NTHREADS, 2)
tgs_kernel(const float* __restrict__ node_features,
           const float* __restrict__ timestamps,
           const float* __restrict__ edge_features,
           const int*   __restrict__ neighbors,
           const int*   __restrict__ edge_idxs,
           const float* __restrict__ edge_times,
           const float* __restrict__ time_w,
           const float* __restrict__ time_b,
           const float* __restrict__ W1,
           const float* __restrict__ b1,
           const float* __restrict__ W2,
           const float* __restrict__ b2,
           float* __restrict__ out) {
    extern __shared__ float sm[];
    float* Ws = sm + WS_OFF;

    const int tid  = threadIdx.x;
    const int lane = tid & 31;
    const int wid  = tid >> 5;

    if (wid >= 8) {
        // ============================ PRODUCERS (warps 8..11) ============================
        const int pw = wid - 8;
        const ulonglong2 tw2 = *(const ulonglong2*)(time_w + lane * 4);
        const ulonglong2 tb2 = *(const ulonglong2*)(time_b + lane * 4);
        const u64 INVPI2  = pack2(0.31830988618379067f);
        const u64 MAGIC2  = pack2(12582912.0f);
        const u64 NMAGIC2 = pack2(-12582912.0f);
        const u64 P1N2 = pack2(-3.140625f);
        const u64 P2N2 = pack2(-9.67502593994140625e-4f);
        const u64 P3N2 = pack2(-1.5099579909783764e-7f);

        int pt = 0;
        for (int t = blockIdx.x; t < N_TILES; t += GRID, ++pt) {
            const int buf = pt & 1;
            if (pt >= 2) BAR_SYNC(3 + buf, NTHREADS);   // wait empty[buf]
            float* aggS = sm + buf * AGGSZ;

#pragma unroll 1
            for (int v = 0; v < 8; ++v) {
                const int m = pw * 8 + v;
                const int n = t * M_TILE + m;
                if (n >= NN) continue;
                u64 an0 = 0, an1 = 0, at0 = 0, at1 = 0, ae0 = 0, ae1 = 0;
                const float tsn  = timestamps[n];
                const int*   nb_p = neighbors  + n * KNBR;
                const int*   ei_p = edge_idxs  + n * KNBR;
                const float* et_p = edge_times + n * KNBR;
#pragma unroll 10
                for (int k = 0; k < KNBR; ++k) {
                    const int   nb = nb_p[k];
                    const int   ei = ei_p[k];
                    const float et = et_p[k];
                    const ulonglong2 f1 = *(const ulonglong2*)(node_features + (size_t)nb * DIM + lane * 4);
                    const ulonglong2 f2 = *(const ulonglong2*)(edge_features + (size_t)ei * DIM + lane * 4);
                    an0 = add2(an0, f1.x); an1 = add2(an1, f1.y);
                    ae0 = add2(ae0, f2.x); ae1 = add2(ae1, f2.y);
                    const u64 dl2 = pack2(tsn - et);
                    const u64 x0 = fma2(dl2, tw2.x, tb2.x);
                    const u64 x1 = fma2(dl2, tw2.y, tb2.y);
                    at0 = add2(at0, cos2(x0, INVPI2, MAGIC2, NMAGIC2, P1N2, P2N2, P3N2));
                    at1 = add2(at1, cos2(x1, INVPI2, MAGIC2, NMAGIC2, P1N2, P2N2, P3N2));
                }
                float* row = aggS + m * AGG_STRIDE + lane * 4;
                ((ulonglong2*)(row))[0]       = make_ulonglong2(an0, an1);
                ((ulonglong2*)(row + 128))[0] = make_ulonglong2(at0, at1);
                ((ulonglong2*)(row + 256))[0] = make_ulonglong2(ae0, ae1);
            }
            asm volatile("membar.cta;" ::: "memory");
            BAR_ARRIVE(1 + buf, NTHREADS);              // signal full[buf]
        }
    } else {
        // ============================ CONSUMERS (warps 0..7) ============================
        const int r8   = lane >> 2;
        const int coff = wid * 16 + (lane & 3) * 4;

        // cvec[c] = b2[c] + sum_d cos(time_b[d]) * W2[256+d][c], stored in agg pads
        if (tid < DIM) Ws[tid] = cosf(time_b[tid]);     // Ws as scratch pre-GEMM
        BAR_SYNC(5, 256);
        if (tid < DIM) {
            float a = b2[tid];
#pragma unroll 16
            for (int d = 0; d < DIM; ++d)
                a = fmaf(Ws[d], W2[(size_t)(2 * DIM + d) * DIM + tid], a);
            float* cp = (tid < 124) ? (sm + (tid >> 2) * AGG_STRIDE + 384 + (tid & 3))
                                    : (sm + AGGSZ + 384 + (tid - 124));
            *cp = a;
        }
        BAR_SYNC(5, 256);
        u64 cv0, cv1;
        {
            const float* cp = (coff < 124) ? (sm + (coff >> 2) * AGG_STRIDE + 384)
                                           : (sm + AGGSZ + 384);
            float4 c4v = *(const float4*)cp;
            cv0 = pack2b(c4v.x, c4v.y);
            cv1 = pack2b(c4v.z, c4v.w);
        }

        int ct = 0;
        for (int t = blockIdx.x; t < N_TILES; t += GRID, ++ct) {
            const int buf = ct & 1;
            float* aggS = sm + buf * AGGSZ;

            float4 wreg[4];
            ldW(W1, 0, wreg);
            BAR_SYNC(1 + buf, NTHREADS);                // wait full[buf]

            // -------- GEMM1: H = relu(agg @ W1 + K*b1), 12 slices --------
            u64 acc[4][2];
#pragma unroll
            for (int i = 0; i < 4; ++i) { acc[i][0] = 0ull; acc[i][1] = 0ull; }
#pragma unroll 1
            for (int s = 0; s < 384 / KK_TILE; ++s) {
                stW(Ws, wreg);
                if (s < 384 / KK_TILE - 1) ldW(W1, s + 1, wreg);
                BAR_SYNC(5, 256);
                gemm_slice(aggS + s * KK_TILE, Ws, r8, coff, acc);
                BAR_SYNC(5, 256);
            }
            ldW(W2, 0, wreg);

            // Epilogue 1: H -> aggS cols [0,128)
            {
                const float4 b1v = *(const float4*)&b1[coff];
#pragma unroll
                for (int i = 0; i < 4; ++i) {
                    float4 h;
                    unpack2(acc[i][0], h.x, h.y);
                    unpack2(acc[i][1], h.z, h.w);
                    h.x = fmaxf(fmaf((float)KNBR, b1v.x, h.x), 0.f);
                    h.y = fmaxf(fmaf((float)KNBR, b1v.y, h.y), 0.f);
                    h.z = fmaxf(fmaf((float)KNBR, b1v.z, h.z), 0.f);
                    h.w = fmaxf(fmaf((float)KNBR, b1v.w, h.w), 0.f);
                    *(float4*)&aggS[(r8 + 8 * i) * AGG_STRIDE + coff] = h;
                }
            }
            // node_features of this tile -> aggS cols [128,256)
            {
                const int m = tid >> 3;
                const int u = tid & 7;
                const int n = t * M_TILE + m;
#pragma unroll
                for (int v2 = 0; v2 < 4; ++v2) {
                    const int col = u * 16 + v2 * 4;
                    float4 val = {0.f, 0.f, 0.f, 0.f};
                    if (n < NN) val = *(const float4*)(node_features + (size_t)n * DIM + col);
                    *(float4*)&aggS[m * AGG_STRIDE + 128 + col] = val;
                }
            }
            BAR_SYNC(5, 256);

            // -------- GEMM2: out = [H | nf] @ W2[0:256] + cvec, 8 slices --------
#pragma unroll
            for (int i = 0; i < 4; ++i) { acc[i][0] = cv0; acc[i][1] = cv1; }
#pragma unroll 1
            for (int s = 0; s < 256 / KK_TILE; ++s) {
                stW(Ws, wreg);
                if (s < 256 / KK_TILE - 1) ldW(W2, s + 1, wreg);
                BAR_SYNC(5, 256);
                gemm_slice(aggS + s * KK_TILE, Ws, r8, coff, acc);
                BAR_SYNC(5, 256);
            }
            BAR_ARRIVE(3 + buf, NTHREADS);              // signal empty[buf] early

#pragma unroll
            for (int i = 0; i < 4; ++i) {
                const int n = t * M_TILE + r8 + 8 * i;
                if (n < NN) {
                    float4 o;
                    unpack2(acc[i][0], o.x, o.y);
                    unpack2(acc[i][1], o.z, o.w);
                    *(float4*)(out + (size_t)n * DIM + coff) = o;
                }
            }
        }
    }
}

extern "C" void kernel_launch(void* const* d_in, const int* in_sizes, int n_in,
                              void* d_out, int out_size) {
    const float* node_features = (const float*)d_in[0];
    const float* timestamps    = (const float*)d_in[1];
    const float* edge_features = (const float*)d_in[2];
    const int*   neighbors     = (const int*)d_in[3];
    const int*   edge_idxs     = (const int*)d_in[4];
    const float* edge_times    = (const float*)d_in[5];
    const float* time_w        = (const float*)d_in[6];
    const float* time_b        = (const float*)d_in[7];
    const float* W1            = (const float*)d_in[8];
    const float* b1            = (const float*)d_in[9];
    const float* W2            = (const float*)d_in[10];
    const float* b2            = (const float*)d_in[11];
    float* out = (float*)d_out;

    cudaFuncSetAttribute(tgs_kernel, cudaFuncAttributeMaxDynamicSharedMemorySize, SMEM_BYTES);

    tgs_kernel<<<GRID, NTHREADS, SMEM_BYTES>>>(
        node_features, timestamps, edge_features, neighbors, edge_idxs,
        edge_times, time_w, time_b, W1, b1, W2, b2, out);
}

// round 6
// speedup vs baseline: 1.0034x; 1.0034x over previous
#include <cuda_runtime.h>

#define NN      30000
#define KNBR    20
#define DIM     128
#define M_TILE  32
#define N_TILES 938                  // ceil(30000/32)
#define GRID    296                  // 2 CTAs/SM * 148 SMs
#define NTHREADS 384                 // 8 consumer warps + 4 producer warps
#define AGG_STRIDE 388               // +4 pad: conflict-free a-loads
#define KK_TILE 32

// agg buffer: rows 0..30 padded (stride 388), row 31 trimmed to 384
#define AGGSZ  (31 * AGG_STRIDE + 384)   // 12412 floats
#define WS_OFF (2 * AGGSZ)               // 24824
#define SMEM_FLOATS (WS_OFF + KK_TILE * DIM)  // 28920
#define SMEM_BYTES (SMEM_FLOATS * 4)          // 115680 -> 2 CTAs/SM

// named barriers: 1,2 = full[buf]; 3,4 = empty[buf]; 5 = consumer-only
#define BAR_SYNC(id, cnt)  asm volatile("bar.sync %0, %1;"   :: "r"(id), "r"(cnt) : "memory")
#define BAR_ARRIVE(id, cnt) asm volatile("bar.arrive %0, %1;" :: "r"(id), "r"(cnt) : "memory")

typedef unsigned long long u64;

__device__ __forceinline__ u64 fma2(u64 a, u64 b, u64 c) {
    u64 d;
    asm("fma.rn.f32x2 %0, %1, %2, %3;" : "=l"(d) : "l"(a), "l"(b), "l"(c));
    return d;
}
__device__ __forceinline__ u64 add2(u64 a, u64 b) {
    u64 d;
    asm("add.rn.f32x2 %0, %1, %2;" : "=l"(d) : "l"(a), "l"(b));
    return d;
}
__device__ __forceinline__ u64 pack2(float x) {
    u64 d;
    unsigned r = __float_as_uint(x);
    asm("mov.b64 %0, {%1, %2};" : "=l"(d) : "r"(r), "r"(r));
    return d;
}
__device__ __forceinline__ u64 pack2b(float lo, float hi) {
    u64 d;
    asm("mov.b64 %0, {%1, %2};" : "=l"(d) : "r"(__float_as_uint(lo)), "r"(__float_as_uint(hi)));
    return d;
}
__device__ __forceinline__ void unpack2(u64 v, float& lo, float& hi) {
    unsigned a, b;
    asm("mov.b64 {%0, %1}, %2;" : "=r"(a), "=r"(b) : "l"(v));
    lo = __uint_as_float(a);
    hi = __uint_as_float(b);
}
__device__ __forceinline__ void unpack2i(u64 v, unsigned& lo, unsigned& hi) {
    asm("mov.b64 {%0, %1}, %2;" : "=r"(lo), "=r"(hi) : "l"(v));
}

// Packed 2-lane cos for x in [0, ~1.2e4]: Cody-Waite mod-pi reduction (q < 2^12
// so q*P1 exact), MUFU.COS on |r|<=pi/2, sign flip by parity of q.
__device__ __forceinline__ u64 cos2(u64 x2, u64 INVPI2, u64 MAGIC2, u64 NMAGIC2,
                                    u64 P1N2, u64 P2N2, u64 P3N2) {
    u64 qm2 = fma2(x2, INVPI2, MAGIC2);
    unsigned iq0, iq1;
    unpack2i(qm2, iq0, iq1);
    u64 q2 = add2(qm2, NMAGIC2);
    u64 r2 = fma2(q2, P1N2, x2);
    r2 = fma2(q2, P2N2, r2);
    r2 = fma2(q2, P3N2, r2);
    float rl, rh;
    unpack2(r2, rl, rh);
    unsigned ul = __float_as_uint(__cosf(rl)) ^ (iq0 << 31);
    unsigned uh = __float_as_uint(__cosf(rh)) ^ (iq1 << 31);
    u64 d;
    asm("mov.b64 %0, {%1, %2};" : "=l"(d) : "r"(ul), "r"(uh));
    return d;
}

// W slice prefetch: KK_TILE*DIM = 4096 floats = 1024 float4 / 256 consumers
__device__ __forceinline__ void ldW(const float* __restrict__ W, int slice, float4 r[4]) {
    const float4* p = (const float4*)(W + slice * KK_TILE * DIM);
#pragma unroll
    for (int j = 0; j < 4; ++j) r[j] = p[threadIdx.x + j * 256];
}
__device__ __forceinline__ void stW(float* Ws, const float4 r[4]) {
    float4* p = (float4*)Ws;
#pragma unroll
    for (int j = 0; j < 4; ++j) p[threadIdx.x + j * 256] = r[j];
}

// 32-deep slice: thread owns rows {r8+8i} and cols [coff, coff+4)
__device__ __forceinline__ void gemm_slice(const float* __restrict__ aS,
                                           const float* __restrict__ Ws,
                                           int r8, int coff,
                                           u64 (&acc)[4][2]) {
#pragma unroll
    for (int kk4 = 0; kk4 < KK_TILE / 4; ++kk4) {
        float a4[4][4];
#pragma unroll
        for (int i = 0; i < 4; ++i)
            *(float4*)a4[i] = *(const float4*)&aS[(r8 + 8 * i) * AGG_STRIDE + kk4 * 4];
        ulonglong2 bv[4];
#pragma unroll
        for (int k = 0; k < 4; ++k)
            bv[k] = *(const ulonglong2*)&Ws[(kk4 * 4 + k) * DIM + coff];
#pragma unroll
        for (int k = 0; k < 4; ++k)
#pragma unroll
            for (int i = 0; i < 4; ++i) {
                u64 aa = pack2(a4[i][k]);
                acc[i][0] = fma2(aa, bv[k].x, acc[i][0]);
                acc[i][1] = fma2(aa, bv[k].y, acc[i][1]);
            }
    }
}

__global__ void __launch_bounds__(NTHREADS, 2)
tgs_kernel(const float* __restrict__ node_features,
           const float* __restrict__ timestamps,
           const float* __restrict__ edge_features,
           const int*   __restrict__ neighbors,
           const int*   __restrict__ edge_idxs,
           const float* __restrict__ edge_times,
           const float* __restrict__ time_w,
           const float* __restrict__ time_b,
           const float* __restrict__ W1,
           const float* __restrict__ b1,
           const float* __restrict__ W2,
           const float* __restrict__ b2,
           float* __restrict__ out) {
    extern __shared__ float sm[];
    float* Ws = sm + WS_OFF;

    const int tid  = threadIdx.x;
    const int lane = tid & 31;
    const int wid  = tid >> 5;

    if (wid >= 8) {
        // ============================ PRODUCERS (warps 8..11) ============================
        const int pw = wid - 8;
        const ulonglong2 tw2 = *(const ulonglong2*)(time_w + lane * 4);
        const ulonglong2 tb2 = *(const ulonglong2*)(time_b + lane * 4);
        const u64 INVPI2  = pack2(0.31830988618379067f);
        const u64 MAGIC2  = pack2(12582912.0f);
        const u64 NMAGIC2 = pack2(-12582912.0f);
        const u64 P1N2 = pack2(-3.140625f);
        const u64 P2N2 = pack2(-9.67502593994140625e-4f);
        const u64 P3N2 = pack2(-1.5099579909783764e-7f);

        int pt = 0;
        for (int t = blockIdx.x; t < N_TILES; t += GRID, ++pt) {
            const int buf = pt & 1;
            if (pt >= 2) BAR_SYNC(3 + buf, NTHREADS);   // wait empty[buf]
            float* aggS = sm + buf * AGGSZ;

#pragma unroll 1
            for (int v = 0; v < 8; ++v) {
                const int m = pw * 8 + v;
                const int n = t * M_TILE + m;
                if (n >= NN) continue;
                u64 an0 = 0, an1 = 0, at0 = 0, at1 = 0, ae0 = 0, ae1 = 0;
                const float tsn  = timestamps[n];
                const int*   nb_p = neighbors  + n * KNBR;
                const int*   ei_p = edge_idxs  + n * KNBR;
                const float* et_p = edge_times + n * KNBR;
#pragma unroll 10
                for (int k = 0; k < KNBR; ++k) {
                    const int   nb = nb_p[k];
                    const int   ei = ei_p[k];
                    const float et = et_p[k];
                    const ulonglong2 f1 = *(const ulonglong2*)(node_features + (size_t)nb * DIM + lane * 4);
                    const ulonglong2 f2 = *(const ulonglong2*)(edge_features + (size_t)ei * DIM + lane * 4);
                    an0 = add2(an0, f1.x); an1 = add2(an1, f1.y);
                    ae0 = add2(ae0, f2.x); ae1 = add2(ae1, f2.y);
                    const u64 dl2 = pack2(tsn - et);
                    const u64 x0 = fma2(dl2, tw2.x, tb2.x);
                    const u64 x1 = fma2(dl2, tw2.y, tb2.y);
                    at0 = add2(at0, cos2(x0, INVPI2, MAGIC2, NMAGIC2, P1N2, P2N2, P3N2));
                    at1 = add2(at1, cos2(x1, INVPI2, MAGIC2, NMAGIC2, P1N2, P2N2, P3N2));
                }
                float* row = aggS + m * AGG_STRIDE + lane * 4;
                ((ulonglong2*)(row))[0]       = make_ulonglong2(an0, an1);
                ((ulonglong2*)(row + 128))[0] = make_ulonglong2(at0, at1);
                ((ulonglong2*)(row + 256))[0] = make_ulonglong2(ae0, ae1);
            }
            asm volatile("membar.cta;" ::: "memory");
            BAR_ARRIVE(1 + buf, NTHREADS);              // signal full[buf]
        }
    } else {
        // ============================ CONSUMERS (warps 0..7) ============================
        const int r8   = lane >> 2;
        const int coff = wid * 16 + (lane & 3) * 4;

        // cvec[c] = b2[c] + sum_d cos(time_b[d]) * W2[256+d][c], stored in agg pads
        if (tid < DIM) Ws[tid] = cosf(time_b[tid]);     // Ws as scratch pre-GEMM
        BAR_SYNC(5, 256);
        if (tid < DIM) {
            float a = b2[tid];
#pragma unroll 16
            for (int d = 0; d < DIM; ++d)
                a = fmaf(Ws[d], W2[(size_t)(2 * DIM + d) * DIM + tid], a);
            float* cp = (tid < 124) ? (sm + (tid >> 2) * AGG_STRIDE + 384 + (tid & 3))
                                    : (sm + AGGSZ + 384 + (tid - 124));
            *cp = a;
        }
        BAR_SYNC(5, 256);
        u64 cv0, cv1;
        {
            const float* cp = (coff < 124) ? (sm + (coff >> 2) * AGG_STRIDE + 384)
                                           : (sm + AGGSZ + 384);
            float4 c4v = *(const float4*)cp;
            cv0 = pack2b(c4v.x, c4v.y);
            cv1 = pack2b(c4v.z, c4v.w);
        }

        int ct = 0;
        for (int t = blockIdx.x; t < N_TILES; t += GRID, ++ct) {
            const int buf = ct & 1;
            float* aggS = sm + buf * AGGSZ;

            float4 wreg[4];
            ldW(W1, 0, wreg);
            BAR_SYNC(1 + buf, NTHREADS);                // wait full[buf]

            // -------- GEMM1: H = relu(agg @ W1 + K*b1), 12 slices --------
            u64 acc[4][2];
#pragma unroll
            for (int i = 0; i < 4; ++i) { acc[i][0] = 0ull; acc[i][1] = 0ull; }
#pragma unroll 1
            for (int s = 0; s < 384 / KK_TILE; ++s) {
                stW(Ws, wreg);
                if (s < 384 / KK_TILE - 1) ldW(W1, s + 1, wreg);
                BAR_SYNC(5, 256);
                gemm_slice(aggS + s * KK_TILE, Ws, r8, coff, acc);
                BAR_SYNC(5, 256);
            }
            ldW(W2, 0, wreg);

            // Epilogue 1: H -> aggS cols [0,128)
            {
                const float4 b1v = *(const float4*)&b1[coff];
#pragma unroll
                for (int i = 0; i < 4; ++i) {
                    float4 h;
                    unpack2(acc[i][0], h.x, h.y);
                    unpack2(acc[i][1], h.z, h.w);
                    h.x = fmaxf(fmaf((float)KNBR, b1v.x, h.x), 0.f);
                    h.y = fmaxf(fmaf((float)KNBR, b1v.y, h.y), 0.f);
                    h.z = fmaxf(fmaf((float)KNBR, b1v.z, h.z), 0.f);
                    h.w = fmaxf(fmaf((float)KNBR, b1v.w, h.w), 0.f);
                    *(float4*)&aggS[(r8 + 8 * i) * AGG_STRIDE + coff] = h;
                }
            }
            // node_features of this tile -> aggS cols [128,256)
            {
                const int m = tid >> 3;
                const int u = tid & 7;
                const int n = t * M_TILE + m;
#pragma unroll
                for (int v2 = 0; v2 < 4; ++v2) {
                    const int col = u * 16 + v2 * 4;
                    float4 val = {0.f, 0.f, 0.f, 0.f};
                    if (n < NN) val = *(const float4*)(node_features + (size_t)n * DIM + col);
                    *(float4*)&aggS[m * AGG_STRIDE + 128 + col] = val;
                }
            }
            BAR_SYNC(5, 256);

            // -------- GEMM2: out = [H | nf] @ W2[0:256] + cvec, 8 slices --------
#pragma unroll
            for (int i = 0; i < 4; ++i) { acc[i][0] = cv0; acc[i][1] = cv1; }
#pragma unroll 1
            for (int s = 0; s < 256 / KK_TILE; ++s) {
                stW(Ws, wreg);
                if (s < 256 / KK_TILE - 1) ldW(W2, s + 1, wreg);
                BAR_SYNC(5, 256);
                gemm_slice(aggS + s * KK_TILE, Ws, r8, coff, acc);
                BAR_SYNC(5, 256);
            }
            BAR_ARRIVE(3 + buf, NTHREADS);              // signal empty[buf] early

#pragma unroll
            for (int i = 0; i < 4; ++i) {
                const int n = t * M_TILE + r8 + 8 * i;
                if (n < NN) {
                    float4 o;
                    unpack2(acc[i][0], o.x, o.y);
                    unpack2(acc[i][1], o.z, o.w);
                    *(float4*)(out + (size_t)n * DIM + coff) = o;
                }
            }
        }
    }
}

extern "C" void kernel_launch(void* const* d_in, const int* in_sizes, int n_in,
                              void* d_out, int out_size) {
    const float* node_features = (const float*)d_in[0];
    const float* timestamps    = (const float*)d_in[1];
    const float* edge_features = (const float*)d_in[2];
    const int*   neighbors     = (const int*)d_in[3];
    const int*   edge_idxs     = (const int*)d_in[4];
    const float* edge_times    = (const float*)d_in[5];
    const float* time_w        = (const float*)d_in[6];
    const float* time_b        = (const float*)d_in[7];
    const float* W1            = (const float*)d_in[8];
    const float* b1            = (const float*)d_in[9];
    const float* W2            = (const float*)d_in[10];
    const float* b2            = (const float*)d_in[11];
    float* out = (float*)d_out;

    cudaFuncSetAttribute(tgs_kernel, cudaFuncAttributeMaxDynamicSharedMemorySize, SMEM_BYTES);

    tgs_kernel<<<GRID, NTHREADS, SMEM_BYTES>>>(
        node_features, timestamps, edge_features, neighbors, edge_idxs,
        edge_times, time_w, time_b, W1, b1, W2, b2, out);
}

// round 9
// speedup vs baseline: 1.2334x; 1.2292x over previous
#include <cuda_runtime.h>
#include <cuda_bf16.h>

#define NN      30000
#define NPAD    30080
#define KNBR    20
#define DD      128
#define K1      384
#define K2      256
#define N_TILES 235

typedef unsigned long long u64;
typedef unsigned int u32;

// ---------------- global scratch (zero-init; rows >= NN stay zero) ----------------
__device__ __nv_bfloat16 g_Ah[(size_t)NPAD * K1];
__device__ __nv_bfloat16 g_Al[(size_t)NPAD * K1];
__device__ __nv_bfloat16 g_W1h[DD * K1];   // [n][k] transposed W1
__device__ __nv_bfloat16 g_W1l[DD * K1];
__device__ __nv_bfloat16 g_W2h[DD * K2];   // [n][k] transposed W2[0:256]
__device__ __nv_bfloat16 g_W2l[DD * K2];
__device__ float g_cv[DD];

// ---------------- helpers ----------------
__device__ __forceinline__ u32 smem_u32(const void* p) {
    u32 a;
    asm("{ .reg .u64 t; cvta.to.shared.u64 t, %1; cvt.u32.u64 %0, t; }" : "=r"(a) : "l"(p));
    return a;
}
#define SWZ(o) ((o) ^ (((o) >> 3) & 0x70))

__device__ __forceinline__ unsigned short bfh(float x) {
    return __bfloat16_as_ushort(__float2bfloat16(x));
}
__device__ __forceinline__ u64 pack4(unsigned short a, unsigned short b,
                                     unsigned short c, unsigned short d) {
    return (u64)a | ((u64)b << 16) | ((u64)c << 32) | ((u64)d << 48);
}
__device__ __forceinline__ void split4(float4 v, u64& hi, u64& lo) {
    __nv_bfloat16 h0 = __float2bfloat16(v.x), h1 = __float2bfloat16(v.y);
    __nv_bfloat16 h2 = __float2bfloat16(v.z), h3 = __float2bfloat16(v.w);
    hi = pack4(__bfloat16_as_ushort(h0), __bfloat16_as_ushort(h1),
               __bfloat16_as_ushort(h2), __bfloat16_as_ushort(h3));
    lo = pack4(bfh(v.x - __bfloat162float(h0)), bfh(v.y - __bfloat162float(h1)),
               bfh(v.z - __bfloat162float(h2)), bfh(v.w - __bfloat162float(h3)));
}

// cos(x), x in [0,~1.2e4]: Cody-Waite mod-pi (q<2^12 -> q*P1 exact) + MUFU.COS
__device__ __forceinline__ float fast_cos(float x) {
    const float MAGIC = 12582912.0f;
    float qm = fmaf(x, 0.31830988618379067f, MAGIC);
    int iq = __float_as_int(qm);
    float q = qm - MAGIC;
    float r = fmaf(q, -3.140625f, x);
    r = fmaf(q, -9.67502593994140625e-4f, r);
    r = fmaf(q, -1.5099579909783764e-7f, r);
    float c = __cosf(r);
    return __int_as_float(__float_as_int(c) ^ (iq << 31));
}

// ldmatrix (sm_75+). NOTE: both A ([m][k], k contiguous) and B ([n][k], k
// contiguous) fragments for mma.row.col come from the NON-trans variant.
__device__ __forceinline__ void ldsm4(u32 (&r)[4], u32 addr) {
    asm volatile("ldmatrix.sync.aligned.m8n8.x4.shared.b16 {%0,%1,%2,%3}, [%4];"
                 : "=r"(r[0]), "=r"(r[1]), "=r"(r[2]), "=r"(r[3]) : "r"(addr));
}
// HMMA m16n8k16 bf16 (sm_80+)
__device__ __forceinline__ void mma16816(float (&c)[4], const u32 (&a)[4], u32 b0, u32 b1) {
    asm volatile(
        "mma.sync.aligned.m16n8k16.row.col.f32.bf16.bf16.f32 "
        "{%0,%1,%2,%3}, {%4,%5,%6,%7}, {%8,%9}, {%0,%1,%2,%3};"
        : "+f"(c[0]), "+f"(c[1]), "+f"(c[2]), "+f"(c[3])
        : "r"(a[0]), "r"(a[1]), "r"(a[2]), "r"(a[3]), "r"(b0), "r"(b1));
}

// ============================ prep: W transpose + split ============================
__global__ void __launch_bounds__(256)
prep_kernel(const float* __restrict__ W1, const float* __restrict__ W2) {
    int idx = blockIdx.x * 256 + threadIdx.x;
    if (blockIdx.x < 192) {                       // W1: [384][128] -> [n][384]
        int k = idx >> 7, n = idx & 127;
        float v = W1[k * DD + n];
        __nv_bfloat16 h = __float2bfloat16(v);
        g_W1h[n * K1 + k] = h;
        g_W1l[n * K1 + k] = __float2bfloat16(v - __bfloat162float(h));
    } else {                                      // W2 rows 0..255 -> [n][256]
        int i2 = idx - 192 * 256;
        int k = i2 >> 7, n = i2 & 127;
        float v = W2[k * DD + n];
        __nv_bfloat16 h = __float2bfloat16(v);
        g_W2h[n * K2 + k] = h;
        g_W2l[n * K2 + k] = __float2bfloat16(v - __bfloat162float(h));
    }
}
// cvec[c] = b2[c] + sum_d cos(time_b[d]) * W2[256+d][c]
__global__ void cvec_kernel(const float* __restrict__ W2, const float* __restrict__ b2,
                            const float* __restrict__ tb) {
    __shared__ float cb[DD];
    int c = threadIdx.x;
    cb[c] = cosf(tb[c]);
    __syncthreads();
    float a = b2[c];
    for (int d = 0; d < DD; ++d)
        a = fmaf(cb[d], W2[(size_t)(2 * DD + d) * DD + c], a);
    g_cv[c] = a;
}

// ============================ gather: K-sums -> bf16 hi/lo ============================
__global__ void __launch_bounds__(256)
agg_kernel(const float* __restrict__ nf, const float* __restrict__ ts,
           const float* __restrict__ ef, const int* __restrict__ nbrs,
           const int* __restrict__ eidx, const float* __restrict__ etim,
           const float* __restrict__ tw, const float* __restrict__ tb) {
    const int lane = threadIdx.x & 31, wid = threadIdx.x >> 5;
    const float4 tw4 = *(const float4*)(tw + lane * 4);
    const float4 tb4 = *(const float4*)(tb + lane * 4);
#pragma unroll
    for (int v = 0; v < 4; ++v) {
        const int n = blockIdx.x * 32 + wid * 4 + v;
        if (n >= NN) continue;
        float4 an = {0,0,0,0}, at = {0,0,0,0}, ae = {0,0,0,0};
        const float tsn = ts[n];
        const int*   nb_p = nbrs + n * KNBR;
        const int*   ei_p = eidx + n * KNBR;
        const float* et_p = etim + n * KNBR;
#pragma unroll 10
        for (int k = 0; k < KNBR; ++k) {
            const int   nb = nb_p[k];
            const int   ei = ei_p[k];
            const float et = et_p[k];
            const float4 f1 = *(const float4*)(nf + (size_t)nb * DD + lane * 4);
            const float4 f2 = *(const float4*)(ef + (size_t)ei * DD + lane * 4);
            an.x += f1.x; an.y += f1.y; an.z += f1.z; an.w += f1.w;
            ae.x += f2.x; ae.y += f2.y; ae.z += f2.z; ae.w += f2.w;
            const float dl = tsn - et;
            at.x += fast_cos(fmaf(dl, tw4.x, tb4.x));
            at.y += fast_cos(fmaf(dl, tw4.y, tb4.y));
            at.z += fast_cos(fmaf(dl, tw4.z, tb4.z));
            at.w += fast_cos(fmaf(dl, tw4.w, tb4.w));
        }
        u64 h, l;
        size_t base = (size_t)n * K1 + lane * 4;
        split4(an, h, l); *(u64*)(g_Ah + base)       = h; *(u64*)(g_Al + base)       = l;
        split4(at, h, l); *(u64*)(g_Ah + base + 128) = h; *(u64*)(g_Al + base + 128) = l;
        split4(ae, h, l); *(u64*)(g_Ah + base + 256) = h; *(u64*)(g_Al + base + 256) = l;
    }
}

// ============================ GEMM kernel (mma.sync bf16 3-pass) ============================
// smem byte offsets; all tiles are [128 rows][64 bf16-cols] = 16384 B, SW128-swizzled
#define SA_H 0
#define SA_L 16384
#define SB_H 32768
#define SB_L 49152
#define SH_H 65536          // H hi: 2 chunks (32768)
#define SH_L 98304          // H lo: 2 chunks (32768)
#define SCV  131072         // cvec fp32 (512)
#define SB1  131584         // b1 fp32 (512)
#define SM_TOTAL 132096

// stage one [128][64] bf16 tile (SW128) from row-major bf16 src
__device__ __forceinline__ void stage_bf16(char* tile, const __nv_bfloat16* __restrict__ src,
                                           int rowStride, int r0, int k0) {
    const int t = threadIdx.x;
#pragma unroll
    for (int i = 0; i < 2; ++i) {
        const int idx = t + i * 512;        // 1024 uint4 total
        const int row = idx >> 3, seg = idx & 7;
        uint4 v = *(const uint4*)(src + (size_t)(r0 + row) * rowStride + k0 + seg * 8);
        *(uint4*)(tile + SWZ(row * 128 + seg * 16)) = v;
    }
}
// stage nf fp32 rows -> split hi/lo bf16 tiles
__device__ __forceinline__ void stage_nf(char* th, char* tl, const float* __restrict__ nf,
                                         int n0, int k0) {
    const int t = threadIdx.x;
#pragma unroll
    for (int i = 0; i < 4; ++i) {
        const int idx = t + i * 512;        // 2048 float4 total
        const int row = idx >> 4, seg = idx & 15;
        const int n = n0 + row;
        float4 v = {0, 0, 0, 0};
        if (n < NN) v = *(const float4*)(nf + (size_t)n * DD + k0 + seg * 4);
        u64 h, l;
        split4(v, h, l);
        const u32 off = SWZ(row * 128 + seg * 8);
        *(u64*)(th + off) = h;
        *(u64*)(tl + off) = l;
    }
}

// one 64-deep K chunk: acc += Ah*Bh + Al*Bh + Ah*Bl  (warp tile 32x32)
__device__ __forceinline__ void mma_chunk(u32 ah_b, u32 al_b, u32 bh_b, u32 bl_b,
                                          int wm, int wn, int lane,
                                          float (&acc)[2][4][4]) {
    const int g = lane >> 3, r = lane & 7;
#pragma unroll
    for (int ks = 0; ks < 4; ++ks) {
        const int kb = ks * 32;             // 16 bf16 = 32 bytes per k16
        u32 ah[2][4], al[2][4], bh[2][4], bl[2][4];
#pragma unroll
        for (int mi = 0; mi < 2; ++mi) {
            const int row = wm * 32 + mi * 16 + (g & 1) * 8 + r;
            const u32 off = SWZ(row * 128 + kb + (g >> 1) * 16);
            ldsm4(ah[mi], ah_b + off);
            ldsm4(al[mi], al_b + off);
        }
#pragma unroll
        for (int gi = 0; gi < 2; ++gi) {    // n16 groups; B is [n][k] -> NON-trans
            const int nrow = wn * 32 + gi * 16 + (g >> 1) * 8 + r;
            const u32 off = SWZ(nrow * 128 + kb + (g & 1) * 16);
            ldsm4(bh[gi], bh_b + off);
            ldsm4(bl[gi], bl_b + off);
        }
#pragma unroll
        for (int mi = 0; mi < 2; ++mi)
#pragma unroll
            for (int nj = 0; nj < 4; ++nj) {
                const int gi = nj >> 1, p = (nj & 1) * 2;
                mma16816(acc[mi][nj], ah[mi], bh[gi][p], bh[gi][p + 1]);
                mma16816(acc[mi][nj], al[mi], bh[gi][p], bh[gi][p + 1]);
                mma16816(acc[mi][nj], ah[mi], bl[gi][p], bl[gi][p + 1]);
            }
    }
}

__global__ void __launch_bounds__(512, 1)
gemm_kernel(const float* __restrict__ nf, const float* __restrict__ b1,
            float* __restrict__ out) {
    extern __shared__ char sm[];
    const u32 smb = smem_u32(sm);
    const int tid = threadIdx.x, lane = tid & 31, wid = tid >> 5;
    const int wm = wid & 3, wn = wid >> 2;        // 4x4 warp grid, 32x32 warp tile
    const int n0 = blockIdx.x * 128;

    if (tid < DD) {
        ((float*)(sm + SCV))[tid] = g_cv[tid];
        ((float*)(sm + SB1))[tid] = b1[tid];
    }

    float acc[2][4][4];
#pragma unroll
    for (int a = 0; a < 2; ++a)
#pragma unroll
        for (int b = 0; b < 4; ++b)
#pragma unroll
            for (int q = 0; q < 4; ++q) acc[a][b][q] = 0.f;

    // ---------------- GEMM1: D = agg @ W1t^T (K=384, 6 chunks) ----------------
#pragma unroll 1
    for (int c = 0; c < 6; ++c) {
        __syncthreads();
        stage_bf16(sm + SA_H, g_Ah, K1, n0, c * 64);
        stage_bf16(sm + SA_L, g_Al, K1, n0, c * 64);
        stage_bf16(sm + SB_H, g_W1h, K1, 0, c * 64);
        stage_bf16(sm + SB_L, g_W1l, K1, 0, c * 64);
        __syncthreads();
        mma_chunk(smb + SA_H, smb + SA_L, smb + SB_H, smb + SB_L, wm, wn, lane, acc);
    }

    // ---------------- Epilogue 1: H = relu(D + 20*b1) -> split hi/lo smem ----------------
    {
        const float* b1s = (const float*)(sm + SB1);
#pragma unroll
        for (int mi = 0; mi < 2; ++mi)
#pragma unroll
            for (int nj = 0; nj < 4; ++nj) {
                const int col = wn * 32 + nj * 8 + (lane & 3) * 2;
                const float bb0 = b1s[col], bb1 = b1s[col + 1];
                const int chunk = col >> 6;
                const int cb = (col & 63) * 2;
#pragma unroll
                for (int half = 0; half < 2; ++half) {
                    const int row = wm * 32 + mi * 16 + (lane >> 2) + half * 8;
                    float h0 = fmaxf(fmaf(20.f, bb0, acc[mi][nj][half * 2]),     0.f);
                    float h1 = fmaxf(fmaf(20.f, bb1, acc[mi][nj][half * 2 + 1]), 0.f);
                    __nv_bfloat16 p0 = __float2bfloat16(h0), p1 = __float2bfloat16(h1);
                    u32 hp = (u32)__bfloat16_as_ushort(p0) | ((u32)__bfloat16_as_ushort(p1) << 16);
                    u32 lp = (u32)bfh(h0 - __bfloat162float(p0)) |
                             ((u32)bfh(h1 - __bfloat162float(p1)) << 16);
                    const u32 off = SWZ(row * 128 + cb);
                    *(u32*)(sm + SH_H + chunk * 16384 + off) = hp;
                    *(u32*)(sm + SH_L + chunk * 16384 + off) = lp;
                }
            }
    }

    // ---------------- GEMM2: D = [H | nf] @ W2t^T + cvec (K=256, 4 chunks) ----------------
    {
        const float* cvs = (const float*)(sm + SCV);
#pragma unroll
        for (int mi = 0; mi < 2; ++mi)
#pragma unroll
            for (int nj = 0; nj < 4; ++nj) {
                const int col = wn * 32 + nj * 8 + (lane & 3) * 2;
                acc[mi][nj][0] = cvs[col];
                acc[mi][nj][1] = cvs[col + 1];
                acc[mi][nj][2] = cvs[col];
                acc[mi][nj][3] = cvs[col + 1];
            }
    }
#pragma unroll 1
    for (int c = 0; c < 4; ++c) {
        __syncthreads();
        u32 ah_b, al_b;
        if (c < 2) {
            ah_b = smb + SH_H + c * 16384;
            al_b = smb + SH_L + c * 16384;
        } else {
            stage_nf(sm + SA_H, sm + SA_L, nf, n0, (c - 2) * 64);
            ah_b = smb + SA_H;
            al_b = smb + SA_L;
        }
        stage_bf16(sm + SB_H, g_W2h, K2, 0, c * 64);
        stage_bf16(sm + SB_L, g_W2l, K2, 0, c * 64);
        __syncthreads();
        mma_chunk(ah_b, al_b, smb + SB_H, smb + SB_L, wm, wn, lane, acc);
    }

    // ---------------- Epilogue 2: out = D ----------------
#pragma unroll
    for (int mi = 0; mi < 2; ++mi)
#pragma unroll
        for (int nj = 0; nj < 4; ++nj) {
            const int col = wn * 32 + nj * 8 + (lane & 3) * 2;
#pragma unroll
            for (int half = 0; half < 2; ++half) {
                const int n = n0 + wm * 32 + mi * 16 + (lane >> 2) + half * 8;
                if (n < NN) {
                    float2 o = {acc[mi][nj][half * 2], acc[mi][nj][half * 2 + 1]};
                    *(float2*)(out + (size_t)n * DD + col) = o;
                }
            }
        }
}

extern "C" void kernel_launch(void* const* d_in, const int* in_sizes, int n_in,
                              void* d_out, int out_size) {
    const float* node_features = (const float*)d_in[0];
    const float* timestamps    = (const float*)d_in[1];
    const float* edge_features = (const float*)d_in[2];
    const int*   neighbors     = (const int*)d_in[3];
    const int*   edge_idxs     = (const int*)d_in[4];
    const float* edge_times    = (const float*)d_in[5];
    const float* time_w        = (const float*)d_in[6];
    const float* time_b        = (const float*)d_in[7];
    const float* W1            = (const float*)d_in[8];
    const float* b1            = (const float*)d_in[9];
    const float* W2            = (const float*)d_in[10];
    const float* b2            = (const float*)d_in[11];
    float* out = (float*)d_out;

    cudaFuncSetAttribute(gemm_kernel, cudaFuncAttributeMaxDynamicSharedMemorySize, SM_TOTAL);

    prep_kernel<<<320, 256>>>(W1, W2);
    cvec_kernel<<<1, 128>>>(W2, b2, time_b);
    agg_kernel<<<(NN + 31) / 32, 256>>>(node_features, timestamps, edge_features,
                                        neighbors, edge_idxs, edge_times, time_w, time_b);
    gemm_kernel<<<N_TILES, 512, SM_TOTAL>>>(node_features, b1, out);
}

// round 10
// speedup vs baseline: 1.3546x; 1.0983x over previous
#include <cuda_runtime.h>
#include <cuda_fp16.h>

#define NN      30000
#define NPAD    30080
#define KNBR    20
#define DD      128
#define K1      384
#define K2      256
#define N_TILES 235

typedef unsigned long long u64;
typedef unsigned int u32;

// ---------------- global scratch (zero-init; rows >= NN stay zero) ----------------
__device__ __half g_Ah[(size_t)NPAD * K1];
__device__ __half g_Al[(size_t)NPAD * K1];
__device__ __half g_W1h[DD * K1];   // [n][k] transposed W1, fp16 (hi only)
__device__ __half g_W2h[DD * K2];   // [n][k] transposed W2[0:256], fp16 (hi only)
__device__ float g_cv[DD];

// ---------------- helpers ----------------
__device__ __forceinline__ u32 smem_u32(const void* p) {
    u32 a;
    asm("{ .reg .u64 t; cvta.to.shared.u64 t, %1; cvt.u32.u64 %0, t; }" : "=r"(a) : "l"(p));
    return a;
}
#define SWZ(o) ((o) ^ (((o) >> 3) & 0x70))

__device__ __forceinline__ u64 pack4(unsigned short a, unsigned short b,
                                     unsigned short c, unsigned short d) {
    return (u64)a | ((u64)b << 16) | ((u64)c << 32) | ((u64)d << 48);
}
// fp16 hi/lo split of 4 floats
__device__ __forceinline__ void split4h(float4 v, u64& hi, u64& lo) {
    __half h0 = __float2half_rn(v.x), h1 = __float2half_rn(v.y);
    __half h2 = __float2half_rn(v.z), h3 = __float2half_rn(v.w);
    hi = pack4(__half_as_ushort(h0), __half_as_ushort(h1),
               __half_as_ushort(h2), __half_as_ushort(h3));
    lo = pack4(__half_as_ushort(__float2half_rn(v.x - __half2float(h0))),
               __half_as_ushort(__float2half_rn(v.y - __half2float(h1))),
               __half_as_ushort(__float2half_rn(v.z - __half2float(h2))),
               __half_as_ushort(__float2half_rn(v.w - __half2float(h3))));
}

// cos(x), x in [0,~1.2e4]: Cody-Waite mod-pi (q<2^12 -> q*P1 exact) + MUFU.COS
__device__ __forceinline__ float fast_cos(float x) {
    const float MAGIC = 12582912.0f;
    float qm = fmaf(x, 0.31830988618379067f, MAGIC);
    int iq = __float_as_int(qm);
    float q = qm - MAGIC;
    float r = fmaf(q, -3.140625f, x);
    r = fmaf(q, -9.67502593994140625e-4f, r);
    r = fmaf(q, -1.5099579909783764e-7f, r);
    float c = __cosf(r);
    return __int_as_float(__float_as_int(c) ^ (iq << 31));
}

// ldmatrix (non-trans for both A[m][k] and B[n][k], k contiguous)
__device__ __forceinline__ void ldsm4(u32 (&r)[4], u32 addr) {
    asm volatile("ldmatrix.sync.aligned.m8n8.x4.shared.b16 {%0,%1,%2,%3}, [%4];"
                 : "=r"(r[0]), "=r"(r[1]), "=r"(r[2]), "=r"(r[3]) : "r"(addr));
}
// HMMA m16n8k16 fp16 inputs, fp32 accumulate
__device__ __forceinline__ void mma16816(float (&c)[4], const u32 (&a)[4], u32 b0, u32 b1) {
    asm volatile(
        "mma.sync.aligned.m16n8k16.row.col.f32.f16.f16.f32 "
        "{%0,%1,%2,%3}, {%4,%5,%6,%7}, {%8,%9}, {%0,%1,%2,%3};"
        : "+f"(c[0]), "+f"(c[1]), "+f"(c[2]), "+f"(c[3])
        : "r"(a[0]), "r"(a[1]), "r"(a[2]), "r"(a[3]), "r"(b0), "r"(b1));
}

// ============================ prep: W transpose (fp16 hi only) ============================
__global__ void __launch_bounds__(256)
prep_kernel(const float* __restrict__ W1, const float* __restrict__ W2) {
    int idx = blockIdx.x * 256 + threadIdx.x;
    if (blockIdx.x < 192) {                       // W1: [384][128] -> [n][384]
        int k = idx >> 7, n = idx & 127;
        g_W1h[n * K1 + k] = __float2half_rn(W1[k * DD + n]);
    } else {                                      // W2 rows 0..255 -> [n][256]
        int i2 = idx - 192 * 256;
        int k = i2 >> 7, n = i2 & 127;
        g_W2h[n * K2 + k] = __float2half_rn(W2[k * DD + n]);
    }
}
// cvec[c] = b2[c] + sum_d cos(time_b[d]) * W2[256+d][c]
__global__ void cvec_kernel(const float* __restrict__ W2, const float* __restrict__ b2,
                            const float* __restrict__ tb) {
    __shared__ float cb[DD];
    int c = threadIdx.x;
    cb[c] = cosf(tb[c]);
    __syncthreads();
    float a = b2[c];
    for (int d = 0; d < DD; ++d)
        a = fmaf(cb[d], W2[(size_t)(2 * DD + d) * DD + c], a);
    g_cv[c] = a;
}

// ============================ gather: K-sums -> fp16 hi/lo ============================
__global__ void __launch_bounds__(256)
agg_kernel(const float* __restrict__ nf, const float* __restrict__ ts,
           const float* __restrict__ ef, const int* __restrict__ nbrs,
           const int* __restrict__ eidx, const float* __restrict__ etim,
           const float* __restrict__ tw, const float* __restrict__ tb) {
    const int lane = threadIdx.x & 31, wid = threadIdx.x >> 5;
    const float4 tw4 = *(const float4*)(tw + lane * 4);
    const float4 tb4 = *(const float4*)(tb + lane * 4);
#pragma unroll
    for (int v = 0; v < 4; ++v) {
        const int n = blockIdx.x * 32 + wid * 4 + v;
        if (n >= NN) continue;
        float4 an = {0,0,0,0}, at = {0,0,0,0}, ae = {0,0,0,0};
        const float tsn = ts[n];
        const int*   nb_p = nbrs + n * KNBR;
        const int*   ei_p = eidx + n * KNBR;
        const float* et_p = etim + n * KNBR;
#pragma unroll 10
        for (int k = 0; k < KNBR; ++k) {
            const int   nb = nb_p[k];
            const int   ei = ei_p[k];
            const float et = et_p[k];
            const float4 f1 = *(const float4*)(nf + (size_t)nb * DD + lane * 4);
            // edge rows are ~unique (E=600k): stream them, keep nf L2-resident
            const float4 f2 = __ldcs((const float4*)(ef + (size_t)ei * DD + lane * 4));
            an.x += f1.x; an.y += f1.y; an.z += f1.z; an.w += f1.w;
            ae.x += f2.x; ae.y += f2.y; ae.z += f2.z; ae.w += f2.w;
            const float dl = tsn - et;
            at.x += fast_cos(fmaf(dl, tw4.x, tb4.x));
            at.y += fast_cos(fmaf(dl, tw4.y, tb4.y));
            at.z += fast_cos(fmaf(dl, tw4.z, tb4.z));
            at.w += fast_cos(fmaf(dl, tw4.w, tb4.w));
        }
        u64 h, l;
        size_t base = (size_t)n * K1 + lane * 4;
        split4h(an, h, l); *(u64*)(g_Ah + base)       = h; *(u64*)(g_Al + base)       = l;
        split4h(at, h, l); *(u64*)(g_Ah + base + 128) = h; *(u64*)(g_Al + base + 128) = l;
        split4h(ae, h, l); *(u64*)(g_Ah + base + 256) = h; *(u64*)(g_Al + base + 256) = l;
    }
}

// ============================ GEMM kernel (mma.sync fp16 2-pass) ============================
// smem byte offsets; tiles are [128 rows][64 fp16-cols] = 16384 B, SW128-swizzled
#define SA_H 0
#define SA_L 16384
#define SB_H 32768
#define SH_H 49152          // H hi: 2 chunks (32768)
#define SH_L 81920          // H lo: 2 chunks (32768)
#define SCV  114688         // cvec fp32 (512)
#define SB1  115200         // b1 fp32 (512)
#define SM_TOTAL 115712

// stage one [128][64] fp16 tile (SW128) from row-major fp16 src
__device__ __forceinline__ void stage_f16(char* tile, const __half* __restrict__ src,
                                          int rowStride, int r0, int k0) {
    const int t = threadIdx.x;
#pragma unroll
    for (int i = 0; i < 2; ++i) {
        const int idx = t + i * 512;        // 1024 uint4 total
        const int row = idx >> 3, seg = idx & 7;
        uint4 v = *(const uint4*)(src + (size_t)(r0 + row) * rowStride + k0 + seg * 8);
        *(uint4*)(tile + SWZ(row * 128 + seg * 16)) = v;
    }
}
// stage nf fp32 rows -> split hi/lo fp16 tiles
__device__ __forceinline__ void stage_nf(char* th, char* tl, const float* __restrict__ nf,
                                         int n0, int k0) {
    const int t = threadIdx.x;
#pragma unroll
    for (int i = 0; i < 4; ++i) {
        const int idx = t + i * 512;        // 2048 float4 total
        const int row = idx >> 4, seg = idx & 15;
        const int n = n0 + row;
        float4 v = {0, 0, 0, 0};
        if (n < NN) v = *(const float4*)(nf + (size_t)n * DD + k0 + seg * 4);
        u64 h, l;
        split4h(v, h, l);
        const u32 off = SWZ(row * 128 + seg * 8);
        *(u64*)(th + off) = h;
        *(u64*)(tl + off) = l;
    }
}

// one 64-deep K chunk: acc += Ah*Bh + Al*Bh  (warp tile 32x32)
__device__ __forceinline__ void mma_chunk(u32 ah_b, u32 al_b, u32 bh_b,
                                          int wm, int wn, int lane,
                                          float (&acc)[2][4][4]) {
    const int g = lane >> 3, r = lane & 7;
#pragma unroll
    for (int ks = 0; ks < 4; ++ks) {
        const int kb = ks * 32;             // 16 fp16 = 32 bytes per k16
        u32 ah[2][4], al[2][4], bh[2][4];
#pragma unroll
        for (int mi = 0; mi < 2; ++mi) {
            const int row = wm * 32 + mi * 16 + (g & 1) * 8 + r;
            const u32 off = SWZ(row * 128 + kb + (g >> 1) * 16);
            ldsm4(ah[mi], ah_b + off);
            ldsm4(al[mi], al_b + off);
        }
#pragma unroll
        for (int gi = 0; gi < 2; ++gi) {    // n16 groups; B is [n][k] -> non-trans
            const int nrow = wn * 32 + gi * 16 + (g >> 1) * 8 + r;
            const u32 off = SWZ(nrow * 128 + kb + (g & 1) * 16);
            ldsm4(bh[gi], bh_b + off);
        }
#pragma unroll
        for (int mi = 0; mi < 2; ++mi)
#pragma unroll
            for (int nj = 0; nj < 4; ++nj) {
                const int gi = nj >> 1, p = (nj & 1) * 2;
                mma16816(acc[mi][nj], ah[mi], bh[gi][p], bh[gi][p + 1]);
                mma16816(acc[mi][nj], al[mi], bh[gi][p], bh[gi][p + 1]);
            }
    }
}

__global__ void __launch_bounds__(512, 1)
gemm_kernel(const float* __restrict__ nf, const float* __restrict__ b1,
            float* __restrict__ out) {
    extern __shared__ char sm[];
    const u32 smb = smem_u32(sm);
    const int tid = threadIdx.x, lane = tid & 31, wid = tid >> 5;
    const int wm = wid & 3, wn = wid >> 2;        // 4x4 warp grid, 32x32 warp tile
    const int n0 = blockIdx.x * 128;

    if (tid < DD) {
        ((float*)(sm + SCV))[tid] = g_cv[tid];
        ((float*)(sm + SB1))[tid] = b1[tid];
    }

    float acc[2][4][4];
#pragma unroll
    for (int a = 0; a < 2; ++a)
#pragma unroll
        for (int b = 0; b < 4; ++b)
#pragma unroll
            for (int q = 0; q < 4; ++q) acc[a][b][q] = 0.f;

    // ---------------- GEMM1: D = agg @ W1t^T (K=384, 6 chunks) ----------------
#pragma unroll 1
    for (int c = 0; c < 6; ++c) {
        __syncthreads();
        stage_f16(sm + SA_H, g_Ah, K1, n0, c * 64);
        stage_f16(sm + SA_L, g_Al, K1, n0, c * 64);
        stage_f16(sm + SB_H, g_W1h, K1, 0, c * 64);
        __syncthreads();
        mma_chunk(smb + SA_H, smb + SA_L, smb + SB_H, wm, wn, lane, acc);
    }

    // ---------------- Epilogue 1: H = relu(D + 20*b1) -> split hi/lo smem ----------------
    {
        const float* b1s = (const float*)(sm + SB1);
#pragma unroll
        for (int mi = 0; mi < 2; ++mi)
#pragma unroll
            for (int nj = 0; nj < 4; ++nj) {
                const int col = wn * 32 + nj * 8 + (lane & 3) * 2;
                const float bb0 = b1s[col], bb1 = b1s[col + 1];
                const int chunk = col >> 6;
                const int cb = (col & 63) * 2;
#pragma unroll
                for (int half = 0; half < 2; ++half) {
                    const int row = wm * 32 + mi * 16 + (lane >> 2) + half * 8;
                    float h0 = fmaxf(fmaf(20.f, bb0, acc[mi][nj][half * 2]),     0.f);
                    float h1 = fmaxf(fmaf(20.f, bb1, acc[mi][nj][half * 2 + 1]), 0.f);
                    __half p0 = __float2half_rn(h0), p1 = __float2half_rn(h1);
                    u32 hp = (u32)__half_as_ushort(p0) | ((u32)__half_as_ushort(p1) << 16);
                    u32 lp = (u32)__half_as_ushort(__float2half_rn(h0 - __half2float(p0))) |
                             ((u32)__half_as_ushort(__float2half_rn(h1 - __half2float(p1))) << 16);
                    const u32 off = SWZ(row * 128 + cb);
                    *(u32*)(sm + SH_H + chunk * 16384 + off) = hp;
                    *(u32*)(sm + SH_L + chunk * 16384 + off) = lp;
                }
            }
    }

    // ---------------- GEMM2: D = [H | nf] @ W2t^T + cvec (K=256, 4 chunks) ----------------
    {
        const float* cvs = (const float*)(sm + SCV);
#pragma unroll
        for (int mi = 0; mi < 2; ++mi)
#pragma unroll
            for (int nj = 0; nj < 4; ++nj) {
                const int col = wn * 32 + nj * 8 + (lane & 3) * 2;
                acc[mi][nj][0] = cvs[col];
                acc[mi][nj][1] = cvs[col + 1];
                acc[mi][nj][2] = cvs[col];
                acc[mi][nj][3] = cvs[col + 1];
            }
    }
#pragma unroll 1
    for (int c = 0; c < 4; ++c) {
        __syncthreads();
        u32 ah_b, al_b;
        if (c < 2) {
            ah_b = smb + SH_H + c * 16384;
            al_b = smb + SH_L + c * 16384;
        } else {
            stage_nf(sm + SA_H, sm + SA_L, nf, n0, (c - 2) * 64);
            ah_b = smb + SA_H;
            al_b = smb + SA_L;
        }
        stage_f16(sm + SB_H, g_W2h, K2, 0, c * 64);
        __syncthreads();
        mma_chunk(ah_b, al_b, smb + SB_H, wm, wn, lane, acc);
    }

    // ---------------- Epilogue 2: out = D ----------------
#pragma unroll
    for (int mi = 0; mi < 2; ++mi)
#pragma unroll
        for (int nj = 0; nj < 4; ++nj) {
            const int col = wn * 32 + nj * 8 + (lane & 3) * 2;
#pragma unroll
            for (int half = 0; half < 2; ++half) {
                const int n = n0 + wm * 32 + mi * 16 + (lane >> 2) + half * 8;
                if (n < NN) {
                    float2 o = {acc[mi][nj][half * 2], acc[mi][nj][half * 2 + 1]};
                    *(float2*)(out + (size_t)n * DD + col) = o;
                }
            }
        }
}

extern "C" void kernel_launch(void* const* d_in, const int* in_sizes, int n_in,
                              void* d_out, int out_size) {
    const float* node_features = (const float*)d_in[0];
    const float* timestamps    = (const float*)d_in[1];
    const float* edge_features = (const float*)d_in[2];
    const int*   neighbors     = (const int*)d_in[3];
    const int*   edge_idxs     = (const int*)d_in[4];
    const float* edge_times    = (const float*)d_in[5];
    const float* time_w        = (const float*)d_in[6];
    const float* time_b        = (const float*)d_in[7];
    const float* W1            = (const float*)d_in[8];
    const float* b1            = (const float*)d_in[9];
    const float* W2            = (const float*)d_in[10];
    const float* b2            = (const float*)d_in[11];
    float* out = (float*)d_out;

    cudaFuncSetAttribute(gemm_kernel, cudaFuncAttributeMaxDynamicSharedMemorySize, SM_TOTAL);

    prep_kernel<<<320, 256>>>(W1, W2);
    cvec_kernel<<<1, 128>>>(W2, b2, time_b);
    agg_kernel<<<(NN + 31) / 32, 256>>>(node_features, timestamps, edge_features,
                                        neighbors, edge_idxs, edge_times, time_w, time_b);
    gemm_kernel<<<N_TILES, 512, SM_TOTAL>>>(node_features, b1, out);
}

// round 11
// speedup vs baseline: 1.9529x; 1.4416x over previous
#include <cuda_runtime.h>
#include <cuda_fp16.h>

#define NN      30000
#define NPAD    30080
#define KNBR    20
#define DD      128
#define K1      384
#define K2      256
#define N_TILES 235

typedef unsigned long long u64;
typedef unsigned int u32;

// ---------------- global scratch (zero-init; rows >= NN stay zero) ----------------
__device__ __half g_Ah[(size_t)NPAD * K1];
__device__ __half g_Al[(size_t)NPAD * K1];
__device__ __half g_W1h[DD * K1];   // [n][k] transposed W1 (fp16 hi)
__device__ __half g_W2h[DD * K2];   // [n][k] transposed W2[0:256] (fp16 hi)
__device__ float g_cv[DD];

// ---------------- helpers ----------------
__device__ __forceinline__ u32 smem_u32(const void* p) {
    u32 a;
    asm("{ .reg .u64 t; cvta.to.shared.u64 t, %1; cvt.u32.u64 %0, t; }" : "=r"(a) : "l"(p));
    return a;
}
#define SWZ(o) ((o) ^ (((o) >> 3) & 0x70))

__device__ __forceinline__ u64 fma2(u64 a, u64 b, u64 c) {
    u64 d;
    asm("fma.rn.f32x2 %0, %1, %2, %3;" : "=l"(d) : "l"(a), "l"(b), "l"(c));
    return d;
}
__device__ __forceinline__ u64 add2(u64 a, u64 b) {
    u64 d;
    asm("add.rn.f32x2 %0, %1, %2;" : "=l"(d) : "l"(a), "l"(b));
    return d;
}
__device__ __forceinline__ u64 pack2(float x) {
    u64 d;
    unsigned r = __float_as_uint(x);
    asm("mov.b64 %0, {%1, %2};" : "=l"(d) : "r"(r), "r"(r));
    return d;
}
__device__ __forceinline__ void unpack2(u64 v, float& lo, float& hi) {
    unsigned a, b;
    asm("mov.b64 {%0, %1}, %2;" : "=r"(a), "=r"(b) : "l"(v));
    lo = __uint_as_float(a);
    hi = __uint_as_float(b);
}
__device__ __forceinline__ void unpack2i(u64 v, unsigned& lo, unsigned& hi) {
    asm("mov.b64 {%0, %1}, %2;" : "=r"(lo), "=r"(hi) : "l"(v));
}

__device__ __forceinline__ u64 pack4(unsigned short a, unsigned short b,
                                     unsigned short c, unsigned short d) {
    return (u64)a | ((u64)b << 16) | ((u64)c << 32) | ((u64)d << 48);
}
// fp16 hi/lo split of 4 floats
__device__ __forceinline__ void split4h(float4 v, u64& hi, u64& lo) {
    __half h0 = __float2half_rn(v.x), h1 = __float2half_rn(v.y);
    __half h2 = __float2half_rn(v.z), h3 = __float2half_rn(v.w);
    hi = pack4(__half_as_ushort(h0), __half_as_ushort(h1),
               __half_as_ushort(h2), __half_as_ushort(h3));
    lo = pack4(__half_as_ushort(__float2half_rn(v.x - __half2float(h0))),
               __half_as_ushort(__float2half_rn(v.y - __half2float(h1))),
               __half_as_ushort(__float2half_rn(v.z - __half2float(h2))),
               __half_as_ushort(__float2half_rn(v.w - __half2float(h3))));
}

// Packed 2-lane cos, x in [0,~1.2e4]: Cody-Waite mod-pi (q<2^12 -> q*P1 exact),
// MUFU.COS on |r|<=pi/2, sign flip by parity of q. (Verified in R5, rel_err 5.5e-7.)
__device__ __forceinline__ u64 cos2(u64 x2, u64 INVPI2, u64 MAGIC2, u64 NMAGIC2,
                                    u64 P1N2, u64 P2N2, u64 P3N2) {
    u64 qm2 = fma2(x2, INVPI2, MAGIC2);
    unsigned iq0, iq1;
    unpack2i(qm2, iq0, iq1);
    u64 q2 = add2(qm2, NMAGIC2);
    u64 r2 = fma2(q2, P1N2, x2);
    r2 = fma2(q2, P2N2, r2);
    r2 = fma2(q2, P3N2, r2);
    float rl, rh;
    unpack2(r2, rl, rh);
    unsigned ul = __float_as_uint(__cosf(rl)) ^ (iq0 << 31);
    unsigned uh = __float_as_uint(__cosf(rh)) ^ (iq1 << 31);
    u64 d;
    asm("mov.b64 %0, {%1, %2};" : "=l"(d) : "r"(ul), "r"(uh));
    return d;
}
// scalar cos for cvec
__device__ __forceinline__ float fast_cos(float x) {
    const float MAGIC = 12582912.0f;
    float qm = fmaf(x, 0.31830988618379067f, MAGIC);
    int iq = __float_as_int(qm);
    float q = qm - MAGIC;
    float r = fmaf(q, -3.140625f, x);
    r = fmaf(q, -9.67502593994140625e-4f, r);
    r = fmaf(q, -1.5099579909783764e-7f, r);
    float c = __cosf(r);
    return __int_as_float(__float_as_int(c) ^ (iq << 31));
}

// ldmatrix (non-trans for both A[m][k] and B[n][k], k contiguous)
__device__ __forceinline__ void ldsm4(u32 (&r)[4], u32 addr) {
    asm volatile("ldmatrix.sync.aligned.m8n8.x4.shared.b16 {%0,%1,%2,%3}, [%4];"
                 : "=r"(r[0]), "=r"(r[1]), "=r"(r[2]), "=r"(r[3]) : "r"(addr));
}
// HMMA m16n8k16 fp16 inputs, fp32 accumulate
__device__ __forceinline__ void mma16816(float (&c)[4], const u32 (&a)[4], u32 b0, u32 b1) {
    asm volatile(
        "mma.sync.aligned.m16n8k16.row.col.f32.f16.f16.f32 "
        "{%0,%1,%2,%3}, {%4,%5,%6,%7}, {%8,%9}, {%0,%1,%2,%3};"
        : "+f"(c[0]), "+f"(c[1]), "+f"(c[2]), "+f"(c[3])
        : "r"(a[0]), "r"(a[1]), "r"(a[2]), "r"(a[3]), "r"(b0), "r"(b1));
}

// ============================ prep: W transpose (fp16 hi only) ============================
__global__ void __launch_bounds__(256)
prep_kernel(const float* __restrict__ W1, const float* __restrict__ W2) {
    int idx = blockIdx.x * 256 + threadIdx.x;
    if (blockIdx.x < 192) {                       // W1: [384][128] -> [n][384]
        int k = idx >> 7, n = idx & 127;
        g_W1h[n * K1 + k] = __float2half_rn(W1[k * DD + n]);
    } else {                                      // W2 rows 0..255 -> [n][256]
        int i2 = idx - 192 * 256;
        int k = i2 >> 7, n = i2 & 127;
        g_W2h[n * K2 + k] = __float2half_rn(W2[k * DD + n]);
    }
}
// cvec[c] = b2[c] + sum_d cos(time_b[d]) * W2[256+d][c]
__global__ void cvec_kernel(const float* __restrict__ W2, const float* __restrict__ b2,
                            const float* __restrict__ tb) {
    __shared__ float cb[DD];
    int c = threadIdx.x;
    cb[c] = fast_cos(fabsf(tb[c]));   // tb = 0 in practice; abs for reducer domain
    __syncthreads();
    float a = b2[c];
    for (int d = 0; d < DD; ++d)
        a = fmaf(cb[d], W2[(size_t)(2 * DD + d) * DD + c], a);
    g_cv[c] = a;
}

// ============================ gather: one node per warp ============================
__global__ void __launch_bounds__(256, 2)
agg_kernel(const float* __restrict__ nf, const float* __restrict__ ts,
           const float* __restrict__ ef, const int* __restrict__ nbrs,
           const int* __restrict__ eidx, const float* __restrict__ etim,
           const float* __restrict__ tw, const float* __restrict__ tb) {
    const int lane = threadIdx.x & 31, wid = threadIdx.x >> 5;
    const int n = blockIdx.x * 8 + wid;           // grid 3750 * 8 warps = 30000 exactly

    const ulonglong2 tw2 = *(const ulonglong2*)(tw + lane * 4);
    const ulonglong2 tb2 = *(const ulonglong2*)(tb + lane * 4);
    const u64 INVPI2  = pack2(0.31830988618379067f);
    const u64 MAGIC2  = pack2(12582912.0f);
    const u64 NMAGIC2 = pack2(-12582912.0f);
    const u64 P1N2 = pack2(-3.140625f);
    const u64 P2N2 = pack2(-9.67502593994140625e-4f);
    const u64 P3N2 = pack2(-1.5099579909783764e-7f);

    // preload ALL indices/times: removes the index->gather address dependency
    int nbv = 0, eiv = 0; float etv = 0.f;
    if (lane < KNBR) {
        nbv = nbrs[n * KNBR + lane];
        eiv = eidx[n * KNBR + lane];
        etv = etim[n * KNBR + lane];
    }
    const float tsn = ts[n];

    u64 an0 = 0, an1 = 0, at0 = 0, at1 = 0, ae0 = 0, ae1 = 0;
#pragma unroll
    for (int k = 0; k < KNBR; ++k) {
        const int   nb = __shfl_sync(0xffffffffu, nbv, k);
        const int   ei = __shfl_sync(0xffffffffu, eiv, k);
        const float et = __shfl_sync(0xffffffffu, etv, k);
        const ulonglong2 f1 = *(const ulonglong2*)(nf + (size_t)nb * DD + lane * 4);
        const float4 f2f = __ldcs((const float4*)(ef + (size_t)ei * DD + lane * 4));
        const ulonglong2 f2 = *(const ulonglong2*)&f2f;
        an0 = add2(an0, f1.x); an1 = add2(an1, f1.y);
        ae0 = add2(ae0, f2.x); ae1 = add2(ae1, f2.y);
        const u64 dl2 = pack2(tsn - et);
        at0 = add2(at0, cos2(fma2(dl2, tw2.x, tb2.x),
                             INVPI2, MAGIC2, NMAGIC2, P1N2, P2N2, P3N2));
        at1 = add2(at1, cos2(fma2(dl2, tw2.y, tb2.y),
                             INVPI2, MAGIC2, NMAGIC2, P1N2, P2N2, P3N2));
    }

    float4 an, at, ae;
    unpack2(an0, an.x, an.y); unpack2(an1, an.z, an.w);
    unpack2(at0, at.x, at.y); unpack2(at1, at.z, at.w);
    unpack2(ae0, ae.x, ae.y); unpack2(ae1, ae.z, ae.w);
    u64 h, l;
    size_t base = (size_t)n * K1 + lane * 4;
    split4h(an, h, l); *(u64*)(g_Ah + base)       = h; *(u64*)(g_Al + base)       = l;
    split4h(at, h, l); *(u64*)(g_Ah + base + 128) = h; *(u64*)(g_Al + base + 128) = l;
    split4h(ae, h, l); *(u64*)(g_Ah + base + 256) = h; *(u64*)(g_Al + base + 256) = l;
}

// ============================ GEMM kernel (fp16 2-pass, 256 thr, 2 CTA/SM) ============================
// smem: SA_H 16K | SA_L 16K | SB 16K | SH 32K | cv 512 | b1 512  = 82944 B
#define SA_H 0
#define SA_L 16384
#define SB   32768
#define SH   49152
#define SCV  81920
#define SB1  82432
#define SM_TOTAL 82944

// stage one [128][64] fp16 tile (SW128) from row-major fp16 src (256 thr)
__device__ __forceinline__ void stage_f16(char* tile, const __half* __restrict__ src,
                                          int rowStride, int r0, int k0) {
    const int t = threadIdx.x;
#pragma unroll
    for (int i = 0; i < 4; ++i) {
        const int idx = t + i * 256;        // 1024 uint4 total
        const int row = idx >> 3, seg = idx & 7;
        uint4 v = *(const uint4*)(src + (size_t)(r0 + row) * rowStride + k0 + seg * 8);
        *(uint4*)(tile + SWZ(row * 128 + seg * 16)) = v;
    }
}
// stage nf fp32 rows -> split hi/lo fp16 tiles (256 thr)
__device__ __forceinline__ void stage_nf(char* th, char* tl, const float* __restrict__ nf,
                                         int n0, int k0) {
    const int t = threadIdx.x;
#pragma unroll
    for (int i = 0; i < 8; ++i) {
        const int idx = t + i * 256;        // 2048 float4 total
        const int row = idx >> 4, seg = idx & 15;
        const int n = n0 + row;
        float4 v = {0, 0, 0, 0};
        if (n < NN) v = *(const float4*)(nf + (size_t)n * DD + k0 + seg * 4);
        u64 h, l;
        split4h(v, h, l);
        const u32 off = SWZ(row * 128 + seg * 8);
        *(u64*)(th + off) = h;
        *(u64*)(tl + off) = l;
    }
}

// one 64-deep K chunk: acc += Ah*Bh + Al*Bh. Warp tile 32 rows x 64 cols.
__device__ __forceinline__ void mma_chunk(u32 ah_b, u32 al_b, u32 bh_b,
                                          int wm, int wn, int lane,
                                          float (&acc)[2][8][4]) {
    const int g = lane >> 3, r = lane & 7;
#pragma unroll
    for (int ks = 0; ks < 4; ++ks) {
        const int kb = ks * 32;             // 16 fp16 = 32 bytes per k16
        u32 ah[2][4], al[2][4], bh[4][4];
#pragma unroll
        for (int mi = 0; mi < 2; ++mi) {
            const int row = wm * 32 + mi * 16 + (g & 1) * 8 + r;
            const u32 off = SWZ(row * 128 + kb + (g >> 1) * 16);
            ldsm4(ah[mi], ah_b + off);
            ldsm4(al[mi], al_b + off);
        }
#pragma unroll
        for (int gi = 0; gi < 4; ++gi) {    // 4 n16 groups = 64 cols
            const int nrow = wn * 64 + gi * 16 + (g >> 1) * 8 + r;
            const u32 off = SWZ(nrow * 128 + kb + (g & 1) * 16);
            ldsm4(bh[gi], bh_b + off);
        }
#pragma unroll
        for (int mi = 0; mi < 2; ++mi)
#pragma unroll
            for (int nj = 0; nj < 8; ++nj) {
                const int gi = nj >> 1, p = (nj & 1) * 2;
                mma16816(acc[mi][nj], ah[mi], bh[gi][p], bh[gi][p + 1]);
                mma16816(acc[mi][nj], al[mi], bh[gi][p], bh[gi][p + 1]);
            }
    }
}

__global__ void __launch_bounds__(256, 2)
gemm_kernel(const float* __restrict__ nf, const float* __restrict__ b1,
            float* __restrict__ out) {
    extern __shared__ char sm[];
    const u32 smb = smem_u32(sm);
    const int tid = threadIdx.x, lane = tid & 31, wid = tid >> 5;
    const int wm = wid & 3, wn = wid >> 2;        // 4x2 warp grid, 32x64 warp tile
    const int n0 = blockIdx.x * 128;

    if (tid < DD) {
        ((float*)(sm + SCV))[tid] = g_cv[tid];
        ((float*)(sm + SB1))[tid] = b1[tid];
    }

    float acc[2][8][4];
#pragma unroll
    for (int a = 0; a < 2; ++a)
#pragma unroll
        for (int b = 0; b < 8; ++b)
#pragma unroll
            for (int q = 0; q < 4; ++q) acc[a][b][q] = 0.f;

    // ---------------- GEMM1: D = agg @ W1t^T (K=384, 6 chunks) ----------------
#pragma unroll 1
    for (int c = 0; c < 6; ++c) {
        __syncthreads();
        stage_f16(sm + SA_H, g_Ah, K1, n0, c * 64);
        stage_f16(sm + SA_L, g_Al, K1, n0, c * 64);
        stage_f16(sm + SB,   g_W1h, K1, 0, c * 64);
        __syncthreads();
        mma_chunk(smb + SA_H, smb + SA_L, smb + SB, wm, wn, lane, acc);
    }
    __syncthreads();   // all warps done reading SA/SH regions before epilogue overwrite

    // ---------------- Epilogue 1: H = relu(D + 20*b1); hi -> SH, lo -> SA ----------------
    {
        const float* b1s = (const float*)(sm + SB1);
        char* th = sm + SH   + wn * 16384;   // chunk index == wn
        char* tl = sm + SA_H + wn * 16384;
#pragma unroll
        for (int mi = 0; mi < 2; ++mi)
#pragma unroll
            for (int nj = 0; nj < 8; ++nj) {
                const int col = wn * 64 + nj * 8 + (lane & 3) * 2;
                const float bb0 = b1s[col], bb1 = b1s[col + 1];
                const int cb = (col & 63) * 2;
#pragma unroll
                for (int half = 0; half < 2; ++half) {
                    const int row = wm * 32 + mi * 16 + (lane >> 2) + half * 8;
                    float h0 = fmaxf(fmaf(20.f, bb0, acc[mi][nj][half * 2]),     0.f);
                    float h1 = fmaxf(fmaf(20.f, bb1, acc[mi][nj][half * 2 + 1]), 0.f);
                    __half p0 = __float2half_rn(h0), p1 = __float2half_rn(h1);
                    u32 hp = (u32)__half_as_ushort(p0) | ((u32)__half_as_ushort(p1) << 16);
                    u32 lp = (u32)__half_as_ushort(__float2half_rn(h0 - __half2float(p0))) |
                             ((u32)__half_as_ushort(__float2half_rn(h1 - __half2float(p1))) << 16);
                    const u32 off = SWZ(row * 128 + cb);
                    *(u32*)(th + off) = hp;
                    *(u32*)(tl + off) = lp;
                }
            }
    }

    // ---------------- GEMM2: D = [H | nf] @ W2t^T + cvec (K=256, 4 chunks) ----------------
    {
        const float* cvs = (const float*)(sm + SCV);
#pragma unroll
        for (int mi = 0; mi < 2; ++mi)
#pragma unroll
            for (int nj = 0; nj < 8; ++nj) {
                const int col = wn * 64 + nj * 8 + (lane & 3) * 2;
                acc[mi][nj][0] = cvs[col];
                acc[mi][nj][1] = cvs[col + 1];
                acc[mi][nj][2] = cvs[col];
                acc[mi][nj][3] = cvs[col + 1];
            }
    }
#pragma unroll 1
    for (int c = 0; c < 4; ++c) {
        __syncthreads();
        const u32 ah_b = smb + SH   + (c & 1) * 16384;  // c0/c1: H chunks; c2/c3: re-staged nf
        const u32 al_b = smb + SA_H + (c & 1) * 16384;
        if (c >= 2)   // H chunk (c-2) fully consumed; safe to overwrite
            stage_nf(sm + SH + (c & 1) * 16384, sm + SA_H + (c & 1) * 16384,
                     nf, n0, (c - 2) * 64);
        stage_f16(sm + SB, g_W2h, K2, 0, c * 64);
        __syncthreads();
        mma_chunk(ah_b, al_b, smb + SB, wm, wn, lane, acc);
    }

    // ---------------- Epilogue 2: out = D ----------------
#pragma unroll
    for (int mi = 0; mi < 2; ++mi)
#pragma unroll
        for (int nj = 0; nj < 8; ++nj) {
            const int col = wn * 64 + nj * 8 + (lane & 3) * 2;
#pragma unroll
            for (int half = 0; half < 2; ++half) {
                const int n = n0 + wm * 32 + mi * 16 + (lane >> 2) + half * 8;
                if (n < NN) {
                    float2 o = {acc[mi][nj][half * 2], acc[mi][nj][half * 2 + 1]};
                    *(float2*)(out + (size_t)n * DD + col) = o;
                }
            }
        }
}

extern "C" void kernel_launch(void* const* d_in, const int* in_sizes, int n_in,
                              void* d_out, int out_size) {
    const float* node_features = (const float*)d_in[0];
    const float* timestamps    = (const float*)d_in[1];
    const float* edge_features = (const float*)d_in[2];
    const int*   neighbors     = (const int*)d_in[3];
    const int*   edge_idxs     = (const int*)d_in[4];
    const float* edge_times    = (const float*)d_in[5];
    const float* time_w        = (const float*)d_in[6];
    const float* time_b        = (const float*)d_in[7];
    const float* W1            = (const float*)d_in[8];
    const float* b1            = (const float*)d_in[9];
    const float* W2            = (const float*)d_in[10];
    const float* b2            = (const float*)d_in[11];
    float* out = (float*)d_out;

    cudaFuncSetAttribute(gemm_kernel, cudaFuncAttributeMaxDynamicSharedMemorySize, SM_TOTAL);

    prep_kernel<<<320, 256>>>(W1, W2);
    cvec_kernel<<<1, 128>>>(W2, b2, time_b);
    agg_kernel<<<3750, 256>>>(node_features, timestamps, edge_features,
                              neighbors, edge_idxs, edge_times, time_w, time_b);
    gemm_kernel<<<N_TILES, 256, SM_TOTAL>>>(node_features, b1, out);
}

// round 12
// speedup vs baseline: 2.4988x; 1.2795x over previous
#include <cuda_runtime.h>
#include <cuda_fp16.h>

#define NN      30000
#define NPAD    30080
#define KNBR    20
#define DD      128
#define K1      384
#define K2      256
#define N_TILES 235

typedef unsigned long long u64;
typedef unsigned int u32;

// ---------------- global scratch (zero-init; rows >= NN stay zero) ----------------
__device__ __half g_Ah[(size_t)NPAD * K1];
__device__ __half g_W1h[DD * K1];   // [n][k] transposed W1 (fp16)
__device__ __half g_W2h[DD * K2];   // [n][k] transposed W2[0:256] (fp16)
__device__ float g_cv[DD];

// ---------------- helpers ----------------
__device__ __forceinline__ u32 smem_u32(const void* p) {
    u32 a;
    asm("{ .reg .u64 t; cvta.to.shared.u64 t, %1; cvt.u32.u64 %0, t; }" : "=r"(a) : "l"(p));
    return a;
}
#define SWZ(o) ((o) ^ (((o) >> 3) & 0x70))

__device__ __forceinline__ u64 fma2(u64 a, u64 b, u64 c) {
    u64 d;
    asm("fma.rn.f32x2 %0, %1, %2, %3;" : "=l"(d) : "l"(a), "l"(b), "l"(c));
    return d;
}
__device__ __forceinline__ u64 add2(u64 a, u64 b) {
    u64 d;
    asm("add.rn.f32x2 %0, %1, %2;" : "=l"(d) : "l"(a), "l"(b));
    return d;
}
__device__ __forceinline__ u64 pack2(float x) {
    u64 d;
    unsigned r = __float_as_uint(x);
    asm("mov.b64 %0, {%1, %2};" : "=l"(d) : "r"(r), "r"(r));
    return d;
}
__device__ __forceinline__ void unpack2(u64 v, float& lo, float& hi) {
    unsigned a, b;
    asm("mov.b64 {%0, %1}, %2;" : "=r"(a), "=r"(b) : "l"(v));
    lo = __uint_as_float(a);
    hi = __uint_as_float(b);
}
__device__ __forceinline__ void unpack2i(u64 v, unsigned& lo, unsigned& hi) {
    asm("mov.b64 {%0, %1}, %2;" : "=r"(lo), "=r"(hi) : "l"(v));
}
__device__ __forceinline__ u64 pack4(unsigned short a, unsigned short b,
                                     unsigned short c, unsigned short d) {
    return (u64)a | ((u64)b << 16) | ((u64)c << 32) | ((u64)d << 48);
}
// fp16 (hi-only) pack of 4 floats
__device__ __forceinline__ u64 hi4(float4 v) {
    return pack4(__half_as_ushort(__float2half_rn(v.x)),
                 __half_as_ushort(__float2half_rn(v.y)),
                 __half_as_ushort(__float2half_rn(v.z)),
                 __half_as_ushort(__float2half_rn(v.w)));
}

// Packed 2-lane cos, x in [0,~1.2e4]: Cody-Waite mod-pi (q<2^12 -> q*P1 exact),
// MUFU.COS on |r|<=pi/2, sign flip by parity of q.
__device__ __forceinline__ u64 cos2(u64 x2, u64 INVPI2, u64 MAGIC2, u64 NMAGIC2,
                                    u64 P1N2, u64 P2N2, u64 P3N2) {
    u64 qm2 = fma2(x2, INVPI2, MAGIC2);
    unsigned iq0, iq1;
    unpack2i(qm2, iq0, iq1);
    u64 q2 = add2(qm2, NMAGIC2);
    u64 r2 = fma2(q2, P1N2, x2);
    r2 = fma2(q2, P2N2, r2);
    r2 = fma2(q2, P3N2, r2);
    float rl, rh;
    unpack2(r2, rl, rh);
    unsigned ul = __float_as_uint(__cosf(rl)) ^ (iq0 << 31);
    unsigned uh = __float_as_uint(__cosf(rh)) ^ (iq1 << 31);
    u64 d;
    asm("mov.b64 %0, {%1, %2};" : "=l"(d) : "r"(ul), "r"(uh));
    return d;
}
// scalar cos
__device__ __forceinline__ float fast_cos(float x) {
    const float MAGIC = 12582912.0f;
    float qm = fmaf(x, 0.31830988618379067f, MAGIC);
    int iq = __float_as_int(qm);
    float q = qm - MAGIC;
    float r = fmaf(q, -3.140625f, x);
    r = fmaf(q, -9.67502593994140625e-4f, r);
    r = fmaf(q, -1.5099579909783764e-7f, r);
    float c = __cosf(r);
    return __int_as_float(__float_as_int(c) ^ (iq << 31));
}

// ldmatrix (non-trans for both A[m][k] and B[n][k], k contiguous)
__device__ __forceinline__ void ldsm4(u32 (&r)[4], u32 addr) {
    asm volatile("ldmatrix.sync.aligned.m8n8.x4.shared.b16 {%0,%1,%2,%3}, [%4];"
                 : "=r"(r[0]), "=r"(r[1]), "=r"(r[2]), "=r"(r[3]) : "r"(addr));
}
// HMMA m16n8k16 fp16 inputs, fp32 accumulate
__device__ __forceinline__ void mma16816(float (&c)[4], const u32 (&a)[4], u32 b0, u32 b1) {
    asm volatile(
        "mma.sync.aligned.m16n8k16.row.col.f32.f16.f16.f32 "
        "{%0,%1,%2,%3}, {%4,%5,%6,%7}, {%8,%9}, {%0,%1,%2,%3};"
        : "+f"(c[0]), "+f"(c[1]), "+f"(c[2]), "+f"(c[3])
        : "r"(a[0]), "r"(a[1]), "r"(a[2]), "r"(a[3]), "r"(b0), "r"(b1));
}
// cp.async 16B global->shared (sm_80 base feature)
__device__ __forceinline__ void cp16(u32 dst, const void* src) {
    asm volatile("cp.async.cg.shared.global [%0], [%1], 16;" :: "r"(dst), "l"(src));
}
#define CP_COMMIT_WAIT() do { \
    asm volatile("cp.async.commit_group;" ::: "memory"); \
    asm volatile("cp.async.wait_group 0;" ::: "memory"); } while (0)

// ============================ prep: W transpose + cvec (merged) ============================
__global__ void __launch_bounds__(256)
prep_kernel(const float* __restrict__ W1, const float* __restrict__ W2,
            const float* __restrict__ b2, const float* __restrict__ tb) {
    if (blockIdx.x < 192) {                       // W1: [384][128] -> [n][384]
        int idx = blockIdx.x * 256 + threadIdx.x;
        int k = idx >> 7, n = idx & 127;
        g_W1h[n * K1 + k] = __float2half_rn(W1[k * DD + n]);
    } else if (blockIdx.x < 320) {                // W2 rows 0..255 -> [n][256]
        int i2 = (blockIdx.x - 192) * 256 + threadIdx.x;
        int k = i2 >> 7, n = i2 & 127;
        g_W2h[n * K2 + k] = __float2half_rn(W2[k * DD + n]);
    } else {                                      // cvec
        __shared__ float cb[DD];
        int c = threadIdx.x;
        if (c < DD) cb[c] = fast_cos(fabsf(tb[c]));
        __syncthreads();
        if (c < DD) {
            float a = b2[c];
            for (int d = 0; d < DD; ++d)
                a = fmaf(cb[d], W2[(size_t)(2 * DD + d) * DD + c], a);
            g_cv[c] = a;
        }
    }
}

// ============================ gather: one node per warp ============================
__global__ void __launch_bounds__(256, 2)
agg_kernel(const float* __restrict__ nf, const float* __restrict__ ts,
           const float* __restrict__ ef, const int* __restrict__ nbrs,
           const int* __restrict__ eidx, const float* __restrict__ etim,
           const float* __restrict__ tw, const float* __restrict__ tb) {
    const int lane = threadIdx.x & 31, wid = threadIdx.x >> 5;
    const int n = blockIdx.x * 8 + wid;           // 3750 * 8 = 30000 exactly

    const ulonglong2 tw2 = *(const ulonglong2*)(tw + lane * 4);
    const ulonglong2 tb2 = *(const ulonglong2*)(tb + lane * 4);
    const u64 INVPI2  = pack2(0.31830988618379067f);
    const u64 MAGIC2  = pack2(12582912.0f);
    const u64 NMAGIC2 = pack2(-12582912.0f);
    const u64 P1N2 = pack2(-3.140625f);
    const u64 P2N2 = pack2(-9.67502593994140625e-4f);
    const u64 P3N2 = pack2(-1.5099579909783764e-7f);

    int nbv = 0, eiv = 0; float etv = 0.f;
    if (lane < KNBR) {
        nbv = nbrs[n * KNBR + lane];
        eiv = eidx[n * KNBR + lane];
        etv = etim[n * KNBR + lane];
    }
    const float tsn = ts[n];

    u64 an0 = 0, an1 = 0, at0 = 0, at1 = 0, ae0 = 0, ae1 = 0;
#pragma unroll
    for (int k = 0; k < KNBR; ++k) {
        const int   nb = __shfl_sync(0xffffffffu, nbv, k);
        const int   ei = __shfl_sync(0xffffffffu, eiv, k);
        const float et = __shfl_sync(0xffffffffu, etv, k);
        const ulonglong2 f1 = *(const ulonglong2*)(nf + (size_t)nb * DD + lane * 4);
        const float4 f2f = __ldcs((const float4*)(ef + (size_t)ei * DD + lane * 4));
        const ulonglong2 f2 = *(const ulonglong2*)&f2f;
        an0 = add2(an0, f1.x); an1 = add2(an1, f1.y);
        ae0 = add2(ae0, f2.x); ae1 = add2(ae1, f2.y);
        const u64 dl2 = pack2(tsn - et);
        at0 = add2(at0, cos2(fma2(dl2, tw2.x, tb2.x),
                             INVPI2, MAGIC2, NMAGIC2, P1N2, P2N2, P3N2));
        at1 = add2(at1, cos2(fma2(dl2, tw2.y, tb2.y),
                             INVPI2, MAGIC2, NMAGIC2, P1N2, P2N2, P3N2));
    }

    float4 an, at, ae;
    unpack2(an0, an.x, an.y); unpack2(an1, an.z, an.w);
    unpack2(at0, at.x, at.y); unpack2(at1, at.z, at.w);
    unpack2(ae0, ae.x, ae.y); unpack2(ae1, ae.z, ae.w);
    size_t base = (size_t)n * K1 + lane * 4;
    *(u64*)(g_Ah + base)       = hi4(an);
    *(u64*)(g_Ah + base + 128) = hi4(at);
    *(u64*)(g_Ah + base + 256) = hi4(ae);
}

// ============================ GEMM kernel (fp16 single-pass) ============================
// smem: SA 16K | SB 16K | SH 32K (H, 2 chunks) | cv 512 | b1 512 = 66560 B
#define SA   0
#define SB   16384
#define SH   32768
#define SCV  65536
#define SB1  66048
#define SM_TOTAL 66560

// stage one [128][64] fp16 tile (SW128) via cp.async (256 thr)
__device__ __forceinline__ void stage_f16(u32 tile, const __half* __restrict__ src,
                                          int rowStride, int r0, int k0) {
    const int t = threadIdx.x;
#pragma unroll
    for (int i = 0; i < 4; ++i) {
        const int idx = t + i * 256;        // 1024 16B segments
        const int row = idx >> 3, seg = idx & 7;
        cp16(tile + SWZ(row * 128 + seg * 16),
             src + (size_t)(r0 + row) * rowStride + k0 + seg * 8);
    }
}
// stage nf fp32 rows -> fp16 tile (conversion; synchronous)
__device__ __forceinline__ void stage_nf(char* th, const float* __restrict__ nf,
                                         int n0, int k0) {
    const int t = threadIdx.x;
#pragma unroll
    for (int i = 0; i < 8; ++i) {
        const int idx = t + i * 256;        // 2048 float4
        const int row = idx >> 4, seg = idx & 15;
        const int n = n0 + row;
        float4 v = {0, 0, 0, 0};
        if (n < NN) v = *(const float4*)(nf + (size_t)n * DD + k0 + seg * 4);
        *(u64*)(th + SWZ(row * 128 + seg * 8)) = hi4(v);
    }
}

// one 64-deep K chunk, single pass A*B. Warp tile 32 rows x 64 cols.
__device__ __forceinline__ void mma_chunk(u32 a_b, u32 b_b,
                                          int wm, int wn, int lane,
                                          float (&acc)[2][8][4]) {
    const int g = lane >> 3, r = lane & 7;
#pragma unroll
    for (int ks = 0; ks < 4; ++ks) {
        const int kb = ks * 32;             // 16 fp16 = 32 B per k16
        u32 a[2][4], bh[4][4];
#pragma unroll
        for (int mi = 0; mi < 2; ++mi) {
            const int row = wm * 32 + mi * 16 + (g & 1) * 8 + r;
            ldsm4(a[mi], a_b + SWZ(row * 128 + kb + (g >> 1) * 16));
        }
#pragma unroll
        for (int gi = 0; gi < 4; ++gi) {
            const int nrow = wn * 64 + gi * 16 + (g >> 1) * 8 + r;
            ldsm4(bh[gi], b_b + SWZ(nrow * 128 + kb + (g & 1) * 16));
        }
#pragma unroll
        for (int mi = 0; mi < 2; ++mi)
#pragma unroll
            for (int nj = 0; nj < 8; ++nj) {
                const int gi = nj >> 1, p = (nj & 1) * 2;
                mma16816(acc[mi][nj], a[mi], bh[gi][p], bh[gi][p + 1]);
            }
    }
}

__global__ void __launch_bounds__(256)
gemm_kernel(const float* __restrict__ nf, const float* __restrict__ b1,
            float* __restrict__ out) {
    extern __shared__ char sm[];
    const u32 smb = smem_u32(sm);
    const int tid = threadIdx.x, lane = tid & 31, wid = tid >> 5;
    const int wm = wid & 3, wn = wid >> 2;        // 4x2 warp grid, 32x64 warp tile
    const int n0 = blockIdx.x * 128;

    if (tid < DD) {
        ((float*)(sm + SCV))[tid] = g_cv[tid];
        ((float*)(sm + SB1))[tid] = b1[tid];
    }

    float acc[2][8][4];
#pragma unroll
    for (int a = 0; a < 2; ++a)
#pragma unroll
        for (int b = 0; b < 8; ++b)
#pragma unroll
            for (int q = 0; q < 4; ++q) acc[a][b][q] = 0.f;

    // ---------------- GEMM1: D = agg @ W1t^T (K=384, 6 chunks) ----------------
#pragma unroll 1
    for (int c = 0; c < 6; ++c) {
        __syncthreads();
        stage_f16(smb + SA, g_Ah, K1, n0, c * 64);
        stage_f16(smb + SB, g_W1h, K1, 0, c * 64);
        CP_COMMIT_WAIT();
        __syncthreads();
        mma_chunk(smb + SA, smb + SB, wm, wn, lane, acc);
    }
    __syncthreads();

    // ---------------- Epilogue 1: H = relu(D + 20*b1) -> SH (fp16) ----------------
    {
        const float* b1s = (const float*)(sm + SB1);
        char* th = sm + SH + wn * 16384;   // chunk index == wn
#pragma unroll
        for (int mi = 0; mi < 2; ++mi)
#pragma unroll
            for (int nj = 0; nj < 8; ++nj) {
                const int col = wn * 64 + nj * 8 + (lane & 3) * 2;
                const float bb0 = b1s[col], bb1 = b1s[col + 1];
                const int cb = (col & 63) * 2;
#pragma unroll
                for (int half = 0; half < 2; ++half) {
                    const int row = wm * 32 + mi * 16 + (lane >> 2) + half * 8;
                    float h0 = fmaxf(fmaf(20.f, bb0, acc[mi][nj][half * 2]),     0.f);
                    float h1 = fmaxf(fmaf(20.f, bb1, acc[mi][nj][half * 2 + 1]), 0.f);
                    u32 hp = (u32)__half_as_ushort(__float2half_rn(h0)) |
                             ((u32)__half_as_ushort(__float2half_rn(h1)) << 16);
                    *(u32*)(th + SWZ(row * 128 + cb)) = hp;
                }
            }
    }

    // ---------------- GEMM2: D = [H | nf] @ W2t^T + cvec (K=256, 4 chunks) ----------------
    {
        const float* cvs = (const float*)(sm + SCV);
#pragma unroll
        for (int mi = 0; mi < 2; ++mi)
#pragma unroll
            for (int nj = 0; nj < 8; ++nj) {
                const int col = wn * 64 + nj * 8 + (lane & 3) * 2;
                acc[mi][nj][0] = cvs[col];
                acc[mi][nj][1] = cvs[col + 1];
                acc[mi][nj][2] = cvs[col];
                acc[mi][nj][3] = cvs[col + 1];
            }
    }
#pragma unroll 1
    for (int c = 0; c < 4; ++c) {
        __syncthreads();
        const u32 a_b = (c < 2) ? (smb + SH + c * 16384) : (smb + SA);
        if (c >= 2) stage_nf(sm + SA, nf, n0, (c - 2) * 64);
        stage_f16(smb + SB, g_W2h, K2, 0, c * 64);
        CP_COMMIT_WAIT();
        __syncthreads();
        mma_chunk(a_b, smb + SB, wm, wn, lane, acc);
    }

    // ---------------- Epilogue 2: out = D ----------------
#pragma unroll
    for (int mi = 0; mi < 2; ++mi)
#pragma unroll
        for (int nj = 0; nj < 8; ++nj) {
            const int col = wn * 64 + nj * 8 + (lane & 3) * 2;
#pragma unroll
            for (int half = 0; half < 2; ++half) {
                const int n = n0 + wm * 32 + mi * 16 + (lane >> 2) + half * 8;
                if (n < NN) {
                    float2 o = {acc[mi][nj][half * 2], acc[mi][nj][half * 2 + 1]};
                    *(float2*)(out + (size_t)n * DD + col) = o;
                }
            }
        }
}

extern "C" void kernel_launch(void* const* d_in, const int* in_sizes, int n_in,
                              void* d_out, int out_size) {
    const float* node_features = (const float*)d_in[0];
    const float* timestamps    = (const float*)d_in[1];
    const float* edge_features = (const float*)d_in[2];
    const int*   neighbors     = (const int*)d_in[3];
    const int*   edge_idxs     = (const int*)d_in[4];
    const float* edge_times    = (const float*)d_in[5];
    const float* time_w        = (const float*)d_in[6];
    const float* time_b        = (const float*)d_in[7];
    const float* W1            = (const float*)d_in[8];
    const float* b1            = (const float*)d_in[9];
    const float* W2            = (const float*)d_in[10];
    const float* b2            = (const float*)d_in[11];
    float* out = (float*)d_out;

    cudaFuncSetAttribute(gemm_kernel, cudaFuncAttributeMaxDynamicSharedMemorySize, SM_TOTAL);

    prep_kernel<<<321, 256>>>(W1, W2, b2, time_b);
    agg_kernel<<<3750, 256>>>(node_features, timestamps, edge_features,
                              neighbors, edge_idxs, edge_times, time_w, time_b);
    gemm_kernel<<<N_TILES, 256, SM_TOTAL>>>(node_features, b1, out);
}

// round 13
// speedup vs baseline: 2.5699x; 1.0285x over previous
#include <cuda_runtime.h>
#include <cuda_fp16.h>

#define NN      30000
#define NPAD    30080
#define KNBR    20
#define DD      128
#define K1      384
#define K2      256
#define N_TILES 235
#define AGG_BLKS 3750

typedef unsigned long long u64;
typedef unsigned int u32;

// ---------------- global scratch (zero-init; rows >= NN stay zero) ----------------
__device__ __half g_Ah[(size_t)NPAD * K1];
__device__ __half g_W1h[DD * K1];   // [n][k] transposed W1 (fp16)
__device__ __half g_W2h[DD * K2];   // [n][k] transposed W2[0:256] (fp16)
__device__ float g_cv[DD];

// ---------------- helpers ----------------
__device__ __forceinline__ u32 smem_u32(const void* p) {
    u32 a;
    asm("{ .reg .u64 t; cvta.to.shared.u64 t, %1; cvt.u32.u64 %0, t; }" : "=r"(a) : "l"(p));
    return a;
}
#define SWZ(o) ((o) ^ (((o) >> 3) & 0x70))

__device__ __forceinline__ u64 fma2(u64 a, u64 b, u64 c) {
    u64 d;
    asm("fma.rn.f32x2 %0, %1, %2, %3;" : "=l"(d) : "l"(a), "l"(b), "l"(c));
    return d;
}
__device__ __forceinline__ u64 add2(u64 a, u64 b) {
    u64 d;
    asm("add.rn.f32x2 %0, %1, %2;" : "=l"(d) : "l"(a), "l"(b));
    return d;
}
__device__ __forceinline__ u64 pack2(float x) {
    u64 d;
    unsigned r = __float_as_uint(x);
    asm("mov.b64 %0, {%1, %2};" : "=l"(d) : "r"(r), "r"(r));
    return d;
}
__device__ __forceinline__ void unpack2(u64 v, float& lo, float& hi) {
    unsigned a, b;
    asm("mov.b64 {%0, %1}, %2;" : "=r"(a), "=r"(b) : "l"(v));
    lo = __uint_as_float(a);
    hi = __uint_as_float(b);
}
__device__ __forceinline__ void unpack2i(u64 v, unsigned& lo, unsigned& hi) {
    asm("mov.b64 {%0, %1}, %2;" : "=r"(lo), "=r"(hi) : "l"(v));
}
__device__ __forceinline__ u64 pack4(unsigned short a, unsigned short b,
                                     unsigned short c, unsigned short d) {
    return (u64)a | ((u64)b << 16) | ((u64)c << 32) | ((u64)d << 48);
}
__device__ __forceinline__ u64 hi4(float4 v) {
    return pack4(__half_as_ushort(__float2half_rn(v.x)),
                 __half_as_ushort(__float2half_rn(v.y)),
                 __half_as_ushort(__float2half_rn(v.z)),
                 __half_as_ushort(__float2half_rn(v.w)));
}

// Packed 2-lane cos, x in [0,~1.2e4]: Cody-Waite mod-pi (q<2^12 -> q*P1 exact),
// MUFU.COS on |r|<=pi/2, sign flip by parity of q.
__device__ __forceinline__ u64 cos2(u64 x2, u64 INVPI2, u64 MAGIC2, u64 NMAGIC2,
                                    u64 P1N2, u64 P2N2, u64 P3N2) {
    u64 qm2 = fma2(x2, INVPI2, MAGIC2);
    unsigned iq0, iq1;
    unpack2i(qm2, iq0, iq1);
    u64 q2 = add2(qm2, NMAGIC2);
    u64 r2 = fma2(q2, P1N2, x2);
    r2 = fma2(q2, P2N2, r2);
    r2 = fma2(q2, P3N2, r2);
    float rl, rh;
    unpack2(r2, rl, rh);
    unsigned ul = __float_as_uint(__cosf(rl)) ^ (iq0 << 31);
    unsigned uh = __float_as_uint(__cosf(rh)) ^ (iq1 << 31);
    u64 d;
    asm("mov.b64 %0, {%1, %2};" : "=l"(d) : "r"(ul), "r"(uh));
    return d;
}
__device__ __forceinline__ float fast_cos(float x) {
    const float MAGIC = 12582912.0f;
    float qm = fmaf(x, 0.31830988618379067f, MAGIC);
    int iq = __float_as_int(qm);
    float q = qm - MAGIC;
    float r = fmaf(q, -3.140625f, x);
    r = fmaf(q, -9.67502593994140625e-4f, r);
    r = fmaf(q, -1.5099579909783764e-7f, r);
    float c = __cosf(r);
    return __int_as_float(__float_as_int(c) ^ (iq << 31));
}

__device__ __forceinline__ void ldsm4(u32 (&r)[4], u32 addr) {
    asm volatile("ldmatrix.sync.aligned.m8n8.x4.shared.b16 {%0,%1,%2,%3}, [%4];"
                 : "=r"(r[0]), "=r"(r[1]), "=r"(r[2]), "=r"(r[3]) : "r"(addr));
}
__device__ __forceinline__ void mma16816(float (&c)[4], const u32 (&a)[4], u32 b0, u32 b1) {
    asm volatile(
        "mma.sync.aligned.m16n8k16.row.col.f32.f16.f16.f32 "
        "{%0,%1,%2,%3}, {%4,%5,%6,%7}, {%8,%9}, {%0,%1,%2,%3};"
        : "+f"(c[0]), "+f"(c[1]), "+f"(c[2]), "+f"(c[3])
        : "r"(a[0]), "r"(a[1]), "r"(a[2]), "r"(a[3]), "r"(b0), "r"(b1));
}
__device__ __forceinline__ void cp16(u32 dst, const void* src) {
    asm volatile("cp.async.cg.shared.global [%0], [%1], 16;" :: "r"(dst), "l"(src));
}
#define CP_COMMIT() asm volatile("cp.async.commit_group;" ::: "memory")
#define CP_WAIT(N)  asm volatile("cp.async.wait_group %0;" :: "n"(N) : "memory")

// ============================ agg + prep (merged grid) ============================
// blocks [0, 3750): gather; [3750, 3942): W1 transpose; [3942, 4070): W2; [4070]: cvec
__global__ void __launch_bounds__(256, 2)
agg_kernel(const float* __restrict__ nf, const float* __restrict__ ts,
           const float* __restrict__ ef, const int* __restrict__ nbrs,
           const int* __restrict__ eidx, const float* __restrict__ etim,
           const float* __restrict__ tw, const float* __restrict__ tb,
           const float* __restrict__ W1, const float* __restrict__ W2,
           const float* __restrict__ b2) {
    const int blk = blockIdx.x;
    if (blk >= AGG_BLKS) {
        const int pb = blk - AGG_BLKS;
        if (pb < 192) {                           // W1: [384][128] -> [n][384]
            int idx = pb * 256 + threadIdx.x;
            int k = idx >> 7, n = idx & 127;
            g_W1h[n * K1 + k] = __float2half_rn(W1[k * DD + n]);
        } else if (pb < 320) {                    // W2 rows 0..255 -> [n][256]
            int i2 = (pb - 192) * 256 + threadIdx.x;
            int k = i2 >> 7, n = i2 & 127;
            g_W2h[n * K2 + k] = __float2half_rn(W2[k * DD + n]);
        } else {                                  // cvec
            __shared__ float cb[DD];
            int c = threadIdx.x;
            if (c < DD) cb[c] = fast_cos(fabsf(tb[c]));
            __syncthreads();
            if (c < DD) {
                float a = b2[c];
                for (int d = 0; d < DD; ++d)
                    a = fmaf(cb[d], W2[(size_t)(2 * DD + d) * DD + c], a);
                g_cv[c] = a;
            }
        }
        return;
    }

    const int lane = threadIdx.x & 31, wid = threadIdx.x >> 5;
    const int n = blk * 8 + wid;                  // 3750 * 8 = 30000 exactly

    const ulonglong2 tw2 = *(const ulonglong2*)(tw + lane * 4);
    const ulonglong2 tb2 = *(const ulonglong2*)(tb + lane * 4);
    const u64 INVPI2  = pack2(0.31830988618379067f);
    const u64 MAGIC2  = pack2(12582912.0f);
    const u64 NMAGIC2 = pack2(-12582912.0f);
    const u64 P1N2 = pack2(-3.140625f);
    const u64 P2N2 = pack2(-9.67502593994140625e-4f);
    const u64 P3N2 = pack2(-1.5099579909783764e-7f);

    int nbv = 0, eiv = 0; float etv = 0.f;
    if (lane < KNBR) {
        nbv = nbrs[n * KNBR + lane];
        eiv = eidx[n * KNBR + lane];
        etv = etim[n * KNBR + lane];
    }
    const float tsn = ts[n];

    u64 an0 = 0, an1 = 0, at0 = 0, at1 = 0, ae0 = 0, ae1 = 0;
#pragma unroll
    for (int k = 0; k < KNBR; ++k) {
        const int   nb = __shfl_sync(0xffffffffu, nbv, k);
        const int   ei = __shfl_sync(0xffffffffu, eiv, k);
        const float et = __shfl_sync(0xffffffffu, etv, k);
        const ulonglong2 f1 = *(const ulonglong2*)(nf + (size_t)nb * DD + lane * 4);
        const float4 f2f = __ldcs((const float4*)(ef + (size_t)ei * DD + lane * 4));
        const ulonglong2 f2 = *(const ulonglong2*)&f2f;
        an0 = add2(an0, f1.x); an1 = add2(an1, f1.y);
        ae0 = add2(ae0, f2.x); ae1 = add2(ae1, f2.y);
        const u64 dl2 = pack2(tsn - et);
        at0 = add2(at0, cos2(fma2(dl2, tw2.x, tb2.x),
                             INVPI2, MAGIC2, NMAGIC2, P1N2, P2N2, P3N2));
        at1 = add2(at1, cos2(fma2(dl2, tw2.y, tb2.y),
                             INVPI2, MAGIC2, NMAGIC2, P1N2, P2N2, P3N2));
    }

    float4 an, at, ae;
    unpack2(an0, an.x, an.y); unpack2(an1, an.z, an.w);
    unpack2(at0, at.x, at.y); unpack2(at1, at.z, at.w);
    unpack2(ae0, ae.x, ae.y); unpack2(ae1, ae.z, ae.w);
    size_t base = (size_t)n * K1 + lane * 4;
    *(u64*)(g_Ah + base)       = hi4(an);
    *(u64*)(g_Ah + base + 128) = hi4(at);
    *(u64*)(g_Ah + base + 256) = hi4(ae);
}

// ============================ GEMM kernel (fp16, double-buffered cp.async) ============================
// smem: SA x2 (32K) | SB x2 (32K) | SH (32K) | cv 512 | b1 512 = 99328 B -> 2 CTAs/SM
#define SA(b)  ((b) * 16384)
#define SBUF(b) (32768 + (b) * 16384)
#define SH     65536
#define SCV    98304
#define SB1    98816
#define SM_TOTAL 99328

__device__ __forceinline__ void stage_f16(u32 tile, const __half* __restrict__ src,
                                          int rowStride, int r0, int k0) {
    const int t = threadIdx.x;
#pragma unroll
    for (int i = 0; i < 4; ++i) {
        const int idx = t + i * 256;        // 1024 16B segments
        const int row = idx >> 3, seg = idx & 7;
        cp16(tile + SWZ(row * 128 + seg * 16),
             src + (size_t)(r0 + row) * rowStride + k0 + seg * 8);
    }
}
__device__ __forceinline__ void stage_nf(char* th, const float* __restrict__ nf,
                                         int n0, int k0) {
    const int t = threadIdx.x;
#pragma unroll
    for (int i = 0; i < 8; ++i) {
        const int idx = t + i * 256;        // 2048 float4
        const int row = idx >> 4, seg = idx & 15;
        const int n = n0 + row;
        float4 v = {0, 0, 0, 0};
        if (n < NN) v = *(const float4*)(nf + (size_t)n * DD + k0 + seg * 4);
        *(u64*)(th + SWZ(row * 128 + seg * 8)) = hi4(v);
    }
}

// one 64-deep K chunk; warp tile 32 rows x 64 cols
__device__ __forceinline__ void mma_chunk(u32 a_b, u32 b_b,
                                          int wm, int wn, int lane,
                                          float (&acc)[2][8][4]) {
    const int g = lane >> 3, r = lane & 7;
#pragma unroll
    for (int ks = 0; ks < 4; ++ks) {
        const int kb = ks * 32;
        u32 a[2][4], bh[4][4];
#pragma unroll
        for (int mi = 0; mi < 2; ++mi) {
            const int row = wm * 32 + mi * 16 + (g & 1) * 8 + r;
            ldsm4(a[mi], a_b + SWZ(row * 128 + kb + (g >> 1) * 16));
        }
#pragma unroll
        for (int gi = 0; gi < 4; ++gi) {
            const int nrow = wn * 64 + gi * 16 + (g >> 1) * 8 + r;
            ldsm4(bh[gi], b_b + SWZ(nrow * 128 + kb + (g & 1) * 16));
        }
#pragma unroll
        for (int mi = 0; mi < 2; ++mi)
#pragma unroll
            for (int nj = 0; nj < 8; ++nj) {
                const int gi = nj >> 1, p = (nj & 1) * 2;
                mma16816(acc[mi][nj], a[mi], bh[gi][p], bh[gi][p + 1]);
            }
    }
}

__global__ void __launch_bounds__(256)
gemm_kernel(const float* __restrict__ nf, const float* __restrict__ b1,
            float* __restrict__ out) {
    extern __shared__ char sm[];
    const u32 smb = smem_u32(sm);
    const int tid = threadIdx.x, lane = tid & 31, wid = tid >> 5;
    const int wm = wid & 3, wn = wid >> 2;        // 4x2 warp grid, 32x64 warp tile
    const int n0 = blockIdx.x * 128;

    if (tid < DD) {
        ((float*)(sm + SCV))[tid] = g_cv[tid];
        ((float*)(sm + SB1))[tid] = b1[tid];
    }

    float acc[2][8][4];
#pragma unroll
    for (int a = 0; a < 2; ++a)
#pragma unroll
        for (int b = 0; b < 8; ++b)
#pragma unroll
            for (int q = 0; q < 4; ++q) acc[a][b][q] = 0.f;

    // ---------------- GEMM1: D = agg @ W1t^T (K=384, 6 chunks, pipelined) ----------------
    stage_f16(smb + SA(0), g_Ah, K1, n0, 0);
    stage_f16(smb + SBUF(0), g_W1h, K1, 0, 0);
    CP_COMMIT();
#pragma unroll 1
    for (int c = 0; c < 6; ++c) {
        const int cb = c & 1;
        if (c < 5) {
            stage_f16(smb + SA(cb ^ 1), g_Ah, K1, n0, (c + 1) * 64);
            stage_f16(smb + SBUF(cb ^ 1), g_W1h, K1, 0, (c + 1) * 64);
            CP_COMMIT();
            CP_WAIT(1);
        } else {
            CP_WAIT(0);
        }
        __syncthreads();
        mma_chunk(smb + SA(cb), smb + SBUF(cb), wm, wn, lane, acc);
        __syncthreads();   // buffer cb reusable at c+2
    }

    // ---------------- Epilogue 1: H = relu(D + 20*b1) -> SH (fp16) ----------------
    {
        const float* b1s = (const float*)(sm + SB1);
        char* th = sm + SH + wn * 16384;   // chunk index == wn
#pragma unroll
        for (int mi = 0; mi < 2; ++mi)
#pragma unroll
            for (int nj = 0; nj < 8; ++nj) {
                const int col = wn * 64 + nj * 8 + (lane & 3) * 2;
                const float bb0 = b1s[col], bb1 = b1s[col + 1];
                const int cbyte = (col & 63) * 2;
#pragma unroll
                for (int half = 0; half < 2; ++half) {
                    const int row = wm * 32 + mi * 16 + (lane >> 2) + half * 8;
                    float h0 = fmaxf(fmaf(20.f, bb0, acc[mi][nj][half * 2]),     0.f);
                    float h1 = fmaxf(fmaf(20.f, bb1, acc[mi][nj][half * 2 + 1]), 0.f);
                    u32 hp = (u32)__half_as_ushort(__float2half_rn(h0)) |
                             ((u32)__half_as_ushort(__float2half_rn(h1)) << 16);
                    *(u32*)(th + SWZ(row * 128 + cbyte)) = hp;
                }
            }
    }

    // ---------------- GEMM2: D = [H | nf] @ W2t^T + cvec (K=256, 4 chunks) ----------------
    {
        const float* cvs = (const float*)(sm + SCV);
#pragma unroll
        for (int mi = 0; mi < 2; ++mi)
#pragma unroll
            for (int nj = 0; nj < 8; ++nj) {
                const int col = wn * 64 + nj * 8 + (lane & 3) * 2;
                acc[mi][nj][0] = cvs[col];
                acc[mi][nj][1] = cvs[col + 1];
                acc[mi][nj][2] = cvs[col];
                acc[mi][nj][3] = cvs[col + 1];
            }
    }
    stage_f16(smb + SBUF(0), g_W2h, K2, 0, 0);
    CP_COMMIT();
#pragma unroll 1
    for (int c = 0; c < 4; ++c) {
        const int cb = c & 1;
        if (c < 3) {
            stage_f16(smb + SBUF(cb ^ 1), g_W2h, K2, 0, (c + 1) * 64);
            CP_COMMIT();
        }
        // A source: H chunks live in SH; nf chunks converted into SA buffers
        if (c >= 2) stage_nf(sm + SA(cb), nf, n0, (c - 2) * 64);
        if (c < 3) CP_WAIT(1); else CP_WAIT(0);
        __syncthreads();
        const u32 a_b = (c < 2) ? (smb + SH + c * 16384) : (smb + SA(cb));
        mma_chunk(a_b, smb + SBUF(cb), wm, wn, lane, acc);
        __syncthreads();
    }

    // ---------------- Epilogue 2: out = D ----------------
#pragma unroll
    for (int mi = 0; mi < 2; ++mi)
#pragma unroll
        for (int nj = 0; nj < 8; ++nj) {
            const int col = wn * 64 + nj * 8 + (lane & 3) * 2;
#pragma unroll
            for (int half = 0; half < 2; ++half) {
                const int n = n0 + wm * 32 + mi * 16 + (lane >> 2) + half * 8;
                if (n < NN) {
                    float2 o = {acc[mi][nj][half * 2], acc[mi][nj][half * 2 + 1]};
                    *(float2*)(out + (size_t)n * DD + col) = o;
                }
            }
        }
}

extern "C" void kernel_launch(void* const* d_in, const int* in_sizes, int n_in,
                              void* d_out, int out_size) {
    const float* node_features = (const float*)d_in[0];
    const float* timestamps    = (const float*)d_in[1];
    const float* edge_features = (const float*)d_in[2];
    const int*   neighbors     = (const int*)d_in[3];
    const int*   edge_idxs     = (const int*)d_in[4];
    const float* edge_times    = (const float*)d_in[5];
    const float* time_w        = (const float*)d_in[6];
    const float* time_b        = (const float*)d_in[7];
    const float* W1            = (const float*)d_in[8];
    const float* b1            = (const float*)d_in[9];
    const float* W2            = (const float*)d_in[10];
    const float* b2            = (const float*)d_in[11];
    float* out = (float*)d_out;

    cudaFuncSetAttribute(gemm_kernel, cudaFuncAttributeMaxDynamicSharedMemorySize, SM_TOTAL);

    agg_kernel<<<AGG_BLKS + 321, 256>>>(node_features, timestamps, edge_features,
                                        neighbors, edge_idxs, edge_times, time_w, time_b,
                                        W1, W2, b2);
    gemm_kernel<<<N_TILES, 256, SM_TOTAL>>>(node_features, b1, out);
}

// round 14
// speedup vs baseline: 2.7473x; 1.0690x over previous
#include <cuda_runtime.h>
#include <cuda_fp16.h>

#define NN      30000
#define NPAD    30080
#define KNBR    20
#define DD      128
#define K1      384
#define K2      256
#define M_TILE  64
#define N_TILES 469
#define AGG_BLKS 3750

typedef unsigned long long u64;
typedef unsigned int u32;

// ---------------- global scratch (zero-init; rows >= NN stay zero) ----------------
__device__ __half g_Ah[(size_t)NPAD * K1];
__device__ __half g_W1h[DD * K1];   // [n][k] transposed W1 (fp16)
__device__ __half g_W2h[DD * K2];   // [n][k] transposed W2[0:256] (fp16)
__device__ float g_cv[DD];

// ---------------- helpers ----------------
__device__ __forceinline__ u32 smem_u32(const void* p) {
    u32 a;
    asm("{ .reg .u64 t; cvta.to.shared.u64 t, %1; cvt.u32.u64 %0, t; }" : "=r"(a) : "l"(p));
    return a;
}
#define SWZ(o) ((o) ^ (((o) >> 3) & 0x70))

__device__ __forceinline__ u64 fma2(u64 a, u64 b, u64 c) {
    u64 d;
    asm("fma.rn.f32x2 %0, %1, %2, %3;" : "=l"(d) : "l"(a), "l"(b), "l"(c));
    return d;
}
__device__ __forceinline__ u64 add2(u64 a, u64 b) {
    u64 d;
    asm("add.rn.f32x2 %0, %1, %2;" : "=l"(d) : "l"(a), "l"(b));
    return d;
}
__device__ __forceinline__ u64 pack2(float x) {
    u64 d;
    unsigned r = __float_as_uint(x);
    asm("mov.b64 %0, {%1, %2};" : "=l"(d) : "r"(r), "r"(r));
    return d;
}
__device__ __forceinline__ void unpack2(u64 v, float& lo, float& hi) {
    unsigned a, b;
    asm("mov.b64 {%0, %1}, %2;" : "=r"(a), "=r"(b) : "l"(v));
    lo = __uint_as_float(a);
    hi = __uint_as_float(b);
}
__device__ __forceinline__ void unpack2i(u64 v, unsigned& lo, unsigned& hi) {
    asm("mov.b64 {%0, %1}, %2;" : "=r"(lo), "=r"(hi) : "l"(v));
}
__device__ __forceinline__ u64 pack4(unsigned short a, unsigned short b,
                                     unsigned short c, unsigned short d) {
    return (u64)a | ((u64)b << 16) | ((u64)c << 32) | ((u64)d << 48);
}
__device__ __forceinline__ u64 hi4(float4 v) {
    return pack4(__half_as_ushort(__float2half_rn(v.x)),
                 __half_as_ushort(__float2half_rn(v.y)),
                 __half_as_ushort(__float2half_rn(v.z)),
                 __half_as_ushort(__float2half_rn(v.w)));
}

// Packed 2-lane cos, x in [0,~1.2e4]: Cody-Waite mod-pi (q<2^12 -> q*P1 exact),
// MUFU.COS on |r|<=pi/2, sign flip by parity of q.
__device__ __forceinline__ u64 cos2(u64 x2, u64 INVPI2, u64 MAGIC2, u64 NMAGIC2,
                                    u64 P1N2, u64 P2N2, u64 P3N2) {
    u64 qm2 = fma2(x2, INVPI2, MAGIC2);
    unsigned iq0, iq1;
    unpack2i(qm2, iq0, iq1);
    u64 q2 = add2(qm2, NMAGIC2);
    u64 r2 = fma2(q2, P1N2, x2);
    r2 = fma2(q2, P2N2, r2);
    r2 = fma2(q2, P3N2, r2);
    float rl, rh;
    unpack2(r2, rl, rh);
    unsigned ul = __float_as_uint(__cosf(rl)) ^ (iq0 << 31);
    unsigned uh = __float_as_uint(__cosf(rh)) ^ (iq1 << 31);
    u64 d;
    asm("mov.b64 %0, {%1, %2};" : "=l"(d) : "r"(ul), "r"(uh));
    return d;
}
__device__ __forceinline__ float fast_cos(float x) {
    const float MAGIC = 12582912.0f;
    float qm = fmaf(x, 0.31830988618379067f, MAGIC);
    int iq = __float_as_int(qm);
    float q = qm - MAGIC;
    float r = fmaf(q, -3.140625f, x);
    r = fmaf(q, -9.67502593994140625e-4f, r);
    r = fmaf(q, -1.5099579909783764e-7f, r);
    float c = __cosf(r);
    return __int_as_float(__float_as_int(c) ^ (iq << 31));
}

__device__ __forceinline__ void ldsm4(u32 (&r)[4], u32 addr) {
    asm volatile("ldmatrix.sync.aligned.m8n8.x4.shared.b16 {%0,%1,%2,%3}, [%4];"
                 : "=r"(r[0]), "=r"(r[1]), "=r"(r[2]), "=r"(r[3]) : "r"(addr));
}
__device__ __forceinline__ void mma16816(float (&c)[4], const u32 (&a)[4], u32 b0, u32 b1) {
    asm volatile(
        "mma.sync.aligned.m16n8k16.row.col.f32.f16.f16.f32 "
        "{%0,%1,%2,%3}, {%4,%5,%6,%7}, {%8,%9}, {%0,%1,%2,%3};"
        : "+f"(c[0]), "+f"(c[1]), "+f"(c[2]), "+f"(c[3])
        : "r"(a[0]), "r"(a[1]), "r"(a[2]), "r"(a[3]), "r"(b0), "r"(b1));
}
__device__ __forceinline__ void cp16(u32 dst, const void* src) {
    asm volatile("cp.async.cg.shared.global [%0], [%1], 16;" :: "r"(dst), "l"(src));
}
#define CP_COMMIT() asm volatile("cp.async.commit_group;" ::: "memory")
#define CP_WAIT(N)  asm volatile("cp.async.wait_group %0;" :: "n"(N) : "memory")

// ============================ agg + prep (merged grid) ============================
__global__ void __launch_bounds__(256, 4)
agg_kernel(const float* __restrict__ nf, const float* __restrict__ ts,
           const float* __restrict__ ef, const int* __restrict__ nbrs,
           const int* __restrict__ eidx, const float* __restrict__ etim,
           const float* __restrict__ tw, const float* __restrict__ tb,
           const float* __restrict__ W1, const float* __restrict__ W2,
           const float* __restrict__ b2) {
    const int blk = blockIdx.x;
    if (blk >= AGG_BLKS) {
        const int pb = blk - AGG_BLKS;
        if (pb < 192) {                           // W1: [384][128] -> [n][384]
            int idx = pb * 256 + threadIdx.x;
            int k = idx >> 7, n = idx & 127;
            g_W1h[n * K1 + k] = __float2half_rn(W1[k * DD + n]);
        } else if (pb < 320) {                    // W2 rows 0..255 -> [n][256]
            int i2 = (pb - 192) * 256 + threadIdx.x;
            int k = i2 >> 7, n = i2 & 127;
            g_W2h[n * K2 + k] = __float2half_rn(W2[k * DD + n]);
        } else {                                  // cvec
            __shared__ float cb[DD];
            int c = threadIdx.x;
            if (c < DD) cb[c] = fast_cos(fabsf(tb[c]));
            __syncthreads();
            if (c < DD) {
                float a = b2[c];
                for (int d = 0; d < DD; ++d)
                    a = fmaf(cb[d], W2[(size_t)(2 * DD + d) * DD + c], a);
                g_cv[c] = a;
            }
        }
        return;
    }

    const int lane = threadIdx.x & 31, wid = threadIdx.x >> 5;
    const int n = blk * 8 + wid;                  // 3750 * 8 = 30000 exactly

    const ulonglong2 tw2 = *(const ulonglong2*)(tw + lane * 4);
    const ulonglong2 tb2 = *(const ulonglong2*)(tb + lane * 4);
    const u64 INVPI2  = pack2(0.31830988618379067f);
    const u64 MAGIC2  = pack2(12582912.0f);
    const u64 NMAGIC2 = pack2(-12582912.0f);
    const u64 P1N2 = pack2(-3.140625f);
    const u64 P2N2 = pack2(-9.67502593994140625e-4f);
    const u64 P3N2 = pack2(-1.5099579909783764e-7f);

    int nbv = 0, eiv = 0; float etv = 0.f;
    if (lane < KNBR) {
        nbv = nbrs[n * KNBR + lane];
        eiv = eidx[n * KNBR + lane];
        etv = etim[n * KNBR + lane];
    }
    const float tsn = ts[n];

    u64 an0 = 0, an1 = 0, at0 = 0, at1 = 0, ae0 = 0, ae1 = 0;
#pragma unroll
    for (int k = 0; k < KNBR; ++k) {
        const int   nb = __shfl_sync(0xffffffffu, nbv, k);
        const int   ei = __shfl_sync(0xffffffffu, eiv, k);
        const float et = __shfl_sync(0xffffffffu, etv, k);
        const ulonglong2 f1 = *(const ulonglong2*)(nf + (size_t)nb * DD + lane * 4);
        const float4 f2f = __ldcs((const float4*)(ef + (size_t)ei * DD + lane * 4));
        const ulonglong2 f2 = *(const ulonglong2*)&f2f;
        an0 = add2(an0, f1.x); an1 = add2(an1, f1.y);
        ae0 = add2(ae0, f2.x); ae1 = add2(ae1, f2.y);
        const u64 dl2 = pack2(tsn - et);
        at0 = add2(at0, cos2(fma2(dl2, tw2.x, tb2.x),
                             INVPI2, MAGIC2, NMAGIC2, P1N2, P2N2, P3N2));
        at1 = add2(at1, cos2(fma2(dl2, tw2.y, tb2.y),
                             INVPI2, MAGIC2, NMAGIC2, P1N2, P2N2, P3N2));
    }

    float4 an, at, ae;
    unpack2(an0, an.x, an.y); unpack2(an1, an.z, an.w);
    unpack2(at0, at.x, at.y); unpack2(at1, at.z, at.w);
    unpack2(ae0, ae.x, ae.y); unpack2(ae1, ae.z, ae.w);
    size_t base = (size_t)n * K1 + lane * 4;
    *(u64*)(g_Ah + base)       = hi4(an);
    *(u64*)(g_Ah + base + 128) = hi4(at);
    *(u64*)(g_Ah + base + 256) = hi4(ae);
}

// ============================ GEMM kernel (64-row tiles, 3 CTAs/SM) ============================
// smem: SA x2 (16K) | SB x2 (32K) | SH (16K) | cv 512 | b1 512 = 66560 B
#define SA(b)   ((b) * 8192)
#define SBUF(b) (16384 + (b) * 16384)
#define SH      49152
#define SCV     65536
#define SB1     66048
#define SM_TOTAL 66560

// A tile [64 rows][64 cols] fp16, SW128, via cp.async
__device__ __forceinline__ void stage_a64(u32 tile, const __half* __restrict__ src,
                                          int rowStride, int r0, int k0) {
    const int t = threadIdx.x;
#pragma unroll
    for (int i = 0; i < 2; ++i) {
        const int idx = t + i * 256;        // 512 16B segments
        const int row = idx >> 3, seg = idx & 7;
        cp16(tile + SWZ(row * 128 + seg * 16),
             src + (size_t)(r0 + row) * rowStride + k0 + seg * 8);
    }
}
// B tile [128 rows][64 cols] fp16, SW128, via cp.async
__device__ __forceinline__ void stage_b128(u32 tile, const __half* __restrict__ src,
                                           int rowStride, int k0) {
    const int t = threadIdx.x;
#pragma unroll
    for (int i = 0; i < 4; ++i) {
        const int idx = t + i * 256;        // 1024 16B segments
        const int row = idx >> 3, seg = idx & 7;
        cp16(tile + SWZ(row * 128 + seg * 16),
             src + (size_t)row * rowStride + k0 + seg * 8);
    }
}
// nf fp32 rows -> fp16 A tile [64][64] (synchronous)
__device__ __forceinline__ void stage_nf64(char* th, const float* __restrict__ nf,
                                           int n0, int k0) {
    const int t = threadIdx.x;
#pragma unroll
    for (int i = 0; i < 4; ++i) {
        const int idx = t + i * 256;        // 1024 float4
        const int row = idx >> 4, seg = idx & 15;
        const int n = n0 + row;
        float4 v = {0, 0, 0, 0};
        if (n < NN) v = *(const float4*)(nf + (size_t)n * DD + k0 + seg * 4);
        *(u64*)(th + SWZ(row * 128 + seg * 8)) = hi4(v);
    }
}

// one 64-deep K chunk; warp tile 32 rows x 32 cols
__device__ __forceinline__ void mma_chunk(u32 a_b, u32 b_b,
                                          int wm, int wn, int lane,
                                          float (&acc)[2][4][4]) {
    const int g = lane >> 3, r = lane & 7;
#pragma unroll
    for (int ks = 0; ks < 4; ++ks) {
        const int kb = ks * 32;
        u32 a[2][4], bh[2][4];
#pragma unroll
        for (int mi = 0; mi < 2; ++mi) {
            const int row = wm * 32 + mi * 16 + (g & 1) * 8 + r;
            ldsm4(a[mi], a_b + SWZ(row * 128 + kb + (g >> 1) * 16));
        }
#pragma unroll
        for (int gi = 0; gi < 2; ++gi) {
            const int nrow = wn * 32 + gi * 16 + (g >> 1) * 8 + r;
            ldsm4(bh[gi], b_b + SWZ(nrow * 128 + kb + (g & 1) * 16));
        }
#pragma unroll
        for (int mi = 0; mi < 2; ++mi)
#pragma unroll
            for (int nj = 0; nj < 4; ++nj) {
                const int gi = nj >> 1, p = (nj & 1) * 2;
                mma16816(acc[mi][nj], a[mi], bh[gi][p], bh[gi][p + 1]);
            }
    }
}

__global__ void __launch_bounds__(256, 3)
gemm_kernel(const float* __restrict__ nf, const float* __restrict__ b1,
            float* __restrict__ out) {
    extern __shared__ char sm[];
    const u32 smb = smem_u32(sm);
    const int tid = threadIdx.x, lane = tid & 31, wid = tid >> 5;
    const int wm = wid & 1, wn = wid >> 1;        // 2x4 warp grid, 32x32 warp tile
    const int n0 = blockIdx.x * M_TILE;

    if (tid < DD) {
        ((float*)(sm + SCV))[tid] = g_cv[tid];
        ((float*)(sm + SB1))[tid] = b1[tid];
    }

    float acc[2][4][4];
#pragma unroll
    for (int a = 0; a < 2; ++a)
#pragma unroll
        for (int b = 0; b < 4; ++b)
#pragma unroll
            for (int q = 0; q < 4; ++q) acc[a][b][q] = 0.f;

    // ---------------- GEMM1: D = agg @ W1t^T (K=384, 6 chunks, pipelined) ----------------
    stage_a64(smb + SA(0), g_Ah, K1, n0, 0);
    stage_b128(smb + SBUF(0), g_W1h, K1, 0);
    CP_COMMIT();
#pragma unroll 1
    for (int c = 0; c < 6; ++c) {
        const int cb = c & 1;
        if (c < 5) {
            stage_a64(smb + SA(cb ^ 1), g_Ah, K1, n0, (c + 1) * 64);
            stage_b128(smb + SBUF(cb ^ 1), g_W1h, K1, (c + 1) * 64);
            CP_COMMIT();
            CP_WAIT(1);
        } else {
            CP_WAIT(0);
        }
        __syncthreads();
        mma_chunk(smb + SA(cb), smb + SBUF(cb), wm, wn, lane, acc);
        __syncthreads();
    }

    // ---------------- Epilogue 1: H = relu(D + 20*b1) -> SH (fp16, 2 chunks of [64][64]) ----------------
    {
        const float* b1s = (const float*)(sm + SB1);
#pragma unroll
        for (int mi = 0; mi < 2; ++mi)
#pragma unroll
            for (int nj = 0; nj < 4; ++nj) {
                const int col = wn * 32 + nj * 8 + (lane & 3) * 2;
                const float bb0 = b1s[col], bb1 = b1s[col + 1];
                const int chunk = col >> 6;
                const int cbyte = (col & 63) * 2;
#pragma unroll
                for (int half = 0; half < 2; ++half) {
                    const int row = wm * 32 + mi * 16 + (lane >> 2) + half * 8;
                    float h0 = fmaxf(fmaf(20.f, bb0, acc[mi][nj][half * 2]),     0.f);
                    float h1 = fmaxf(fmaf(20.f, bb1, acc[mi][nj][half * 2 + 1]), 0.f);
                    u32 hp = (u32)__half_as_ushort(__float2half_rn(h0)) |
                             ((u32)__half_as_ushort(__float2half_rn(h1)) << 16);
                    *(u32*)(sm + SH + chunk * 8192 + SWZ(row * 128 + cbyte)) = hp;
                }
            }
    }

    // ---------------- GEMM2: D = [H | nf] @ W2t^T + cvec (K=256, 4 chunks) ----------------
    {
        const float* cvs = (const float*)(sm + SCV);
#pragma unroll
        for (int mi = 0; mi < 2; ++mi)
#pragma unroll
            for (int nj = 0; nj < 4; ++nj) {
                const int col = wn * 32 + nj * 8 + (lane & 3) * 2;
                acc[mi][nj][0] = cvs[col];
                acc[mi][nj][1] = cvs[col + 1];
                acc[mi][nj][2] = cvs[col];
                acc[mi][nj][3] = cvs[col + 1];
            }
    }
    stage_b128(smb + SBUF(0), g_W2h, K2, 0);
    CP_COMMIT();
#pragma unroll 1
    for (int c = 0; c < 4; ++c) {
        const int cb = c & 1;
        if (c < 3) {
            stage_b128(smb + SBUF(cb ^ 1), g_W2h, K2, (c + 1) * 64);
            CP_COMMIT();
        }
        if (c >= 2) stage_nf64(sm + SA(cb), nf, n0, (c - 2) * 64);
        if (c < 3) CP_WAIT(1); else CP_WAIT(0);
        __syncthreads();
        const u32 a_b = (c < 2) ? (smb + SH + c * 8192) : (smb + SA(cb));
        mma_chunk(a_b, smb + SBUF(cb), wm, wn, lane, acc);
        __syncthreads();
    }

    // ---------------- Epilogue 2: out = D ----------------
#pragma unroll
    for (int mi = 0; mi < 2; ++mi)
#pragma unroll
        for (int nj = 0; nj < 4; ++nj) {
            const int col = wn * 32 + nj * 8 + (lane & 3) * 2;
#pragma unroll
            for (int half = 0; half < 2; ++half) {
                const int n = n0 + wm * 32 + mi * 16 + (lane >> 2) + half * 8;
                if (n < NN) {
                    float2 o = {acc[mi][nj][half * 2], acc[mi][nj][half * 2 + 1]};
                    *(float2*)(out + (size_t)n * DD + col) = o;
                }
            }
        }
}

extern "C" void kernel_launch(void* const* d_in, const int* in_sizes, int n_in,
                              void* d_out, int out_size) {
    const float* node_features = (const float*)d_in[0];
    const float* timestamps    = (const float*)d_in[1];
    const float* edge_features = (const float*)d_in[2];
    const int*   neighbors     = (const int*)d_in[3];
    const int*   edge_idxs     = (const int*)d_in[4];
    const float* edge_times    = (const float*)d_in[5];
    const float* time_w        = (const float*)d_in[6];
    const float* time_b        = (const float*)d_in[7];
    const float* W1            = (const float*)d_in[8];
    const float* b1            = (const float*)d_in[9];
    const float* W2            = (const float*)d_in[10];
    const float* b2            = (const float*)d_in[11];
    float* out = (float*)d_out;

    cudaFuncSetAttribute(gemm_kernel, cudaFuncAttributeMaxDynamicSharedMemorySize, SM_TOTAL);

    agg_kernel<<<AGG_BLKS + 321, 256>>>(node_features, timestamps, edge_features,
                                        neighbors, edge_idxs, edge_times, time_w, time_b,
                                        W1, W2, b2);
    gemm_kernel<<<N_TILES, 256, SM_TOTAL>>>(node_features, b1, out);
}

// round 15
// speedup vs baseline: 2.8199x; 1.0264x over previous
#include <cuda_runtime.h>
#include <cuda_fp16.h>

#define NN      30000
#define NPAD    30080
#define KNBR    20
#define DD      128
#define K1      384
#define K2      256
#define N_TILES 235
#define AGG_BLKS 3750

typedef unsigned long long u64;
typedef unsigned int u32;

// ---------------- global scratch (zero-init; rows >= NN stay zero) ----------------
__device__ __half g_Ah[(size_t)NPAD * K1];
__device__ __half g_W1h[DD * K1];   // [n][k] transposed W1 (fp16)
__device__ __half g_W2h[DD * K2];   // [n][k] transposed W2[0:256] (fp16)
__device__ float g_cv[DD];

// ---------------- helpers ----------------
__device__ __forceinline__ u32 smem_u32(const void* p) {
    u32 a;
    asm("{ .reg .u64 t; cvta.to.shared.u64 t, %1; cvt.u32.u64 %0, t; }" : "=r"(a) : "l"(p));
    return a;
}
#define SWZ(o) ((o) ^ (((o) >> 3) & 0x70))

__device__ __forceinline__ u64 fma2(u64 a, u64 b, u64 c) {
    u64 d;
    asm("fma.rn.f32x2 %0, %1, %2, %3;" : "=l"(d) : "l"(a), "l"(b), "l"(c));
    return d;
}
__device__ __forceinline__ u64 add2(u64 a, u64 b) {
    u64 d;
    asm("add.rn.f32x2 %0, %1, %2;" : "=l"(d) : "l"(a), "l"(b));
    return d;
}
__device__ __forceinline__ u64 pack2(float x) {
    u64 d;
    unsigned r = __float_as_uint(x);
    asm("mov.b64 %0, {%1, %2};" : "=l"(d) : "r"(r), "r"(r));
    return d;
}
__device__ __forceinline__ void unpack2(u64 v, float& lo, float& hi) {
    unsigned a, b;
    asm("mov.b64 {%0, %1}, %2;" : "=r"(a), "=r"(b) : "l"(v));
    lo = __uint_as_float(a);
    hi = __uint_as_float(b);
}
__device__ __forceinline__ void unpack2i(u64 v, unsigned& lo, unsigned& hi) {
    asm("mov.b64 {%0, %1}, %2;" : "=r"(lo), "=r"(hi) : "l"(v));
}
__device__ __forceinline__ u64 pack4(unsigned short a, unsigned short b,
                                     unsigned short c, unsigned short d) {
    return (u64)a | ((u64)b << 16) | ((u64)c << 32) | ((u64)d << 48);
}
__device__ __forceinline__ u64 hi4(float4 v) {
    return pack4(__half_as_ushort(__float2half_rn(v.x)),
                 __half_as_ushort(__float2half_rn(v.y)),
                 __half_as_ushort(__float2half_rn(v.z)),
                 __half_as_ushort(__float2half_rn(v.w)));
}

// Packed 2-lane cos, x in [0,~1.2e4]: Cody-Waite mod-pi (q<2^12 -> q*P1 exact),
// MUFU.COS on |r|<=pi/2, sign flip by parity of q.
__device__ __forceinline__ u64 cos2(u64 x2, u64 INVPI2, u64 MAGIC2, u64 NMAGIC2,
                                    u64 P1N2, u64 P2N2, u64 P3N2) {
    u64 qm2 = fma2(x2, INVPI2, MAGIC2);
    unsigned iq0, iq1;
    unpack2i(qm2, iq0, iq1);
    u64 q2 = add2(qm2, NMAGIC2);
    u64 r2 = fma2(q2, P1N2, x2);
    r2 = fma2(q2, P2N2, r2);
    r2 = fma2(q2, P3N2, r2);
    float rl, rh;
    unpack2(r2, rl, rh);
    unsigned ul = __float_as_uint(__cosf(rl)) ^ (iq0 << 31);
    unsigned uh = __float_as_uint(__cosf(rh)) ^ (iq1 << 31);
    u64 d;
    asm("mov.b64 %0, {%1, %2};" : "=l"(d) : "r"(ul), "r"(uh));
    return d;
}
__device__ __forceinline__ float fast_cos(float x) {
    const float MAGIC = 12582912.0f;
    float qm = fmaf(x, 0.31830988618379067f, MAGIC);
    int iq = __float_as_int(qm);
    float q = qm - MAGIC;
    float r = fmaf(q, -3.140625f, x);
    r = fmaf(q, -9.67502593994140625e-4f, r);
    r = fmaf(q, -1.5099579909783764e-7f, r);
    float c = __cosf(r);
    return __int_as_float(__float_as_int(c) ^ (iq << 31));
}

__device__ __forceinline__ void ldsm4(u32 (&r)[4], u32 addr) {
    asm volatile("ldmatrix.sync.aligned.m8n8.x4.shared.b16 {%0,%1,%2,%3}, [%4];"
                 : "=r"(r[0]), "=r"(r[1]), "=r"(r[2]), "=r"(r[3]) : "r"(addr));
}
__device__ __forceinline__ void mma16816(float (&c)[4], const u32 (&a)[4], u32 b0, u32 b1) {
    asm volatile(
        "mma.sync.aligned.m16n8k16.row.col.f32.f16.f16.f32 "
        "{%0,%1,%2,%3}, {%4,%5,%6,%7}, {%8,%9}, {%0,%1,%2,%3};"
        : "+f"(c[0]), "+f"(c[1]), "+f"(c[2]), "+f"(c[3])
        : "r"(a[0]), "r"(a[1]), "r"(a[2]), "r"(a[3]), "r"(b0), "r"(b1));
}
__device__ __forceinline__ void cp16(u32 dst, const void* src) {
    asm volatile("cp.async.cg.shared.global [%0], [%1], 16;" :: "r"(dst), "l"(src));
}
#define CP_COMMIT() asm volatile("cp.async.commit_group;" ::: "memory")
#define CP_WAIT(N)  asm volatile("cp.async.wait_group %0;" :: "n"(N) : "memory")

// ============================ agg + prep (merged grid, 4 CTAs/SM) ============================
__global__ void __launch_bounds__(256, 4)
agg_kernel(const float* __restrict__ nf, const float* __restrict__ ts,
           const float* __restrict__ ef, const int* __restrict__ nbrs,
           const int* __restrict__ eidx, const float* __restrict__ etim,
           const float* __restrict__ tw, const float* __restrict__ tb,
           const float* __restrict__ W1, const float* __restrict__ W2,
           const float* __restrict__ b2) {
    const int blk = blockIdx.x;
    if (blk >= AGG_BLKS) {
        const int pb = blk - AGG_BLKS;
        if (pb < 192) {                           // W1: [384][128] -> [n][384]
            int idx = pb * 256 + threadIdx.x;
            int k = idx >> 7, n = idx & 127;
            g_W1h[n * K1 + k] = __float2half_rn(W1[k * DD + n]);
        } else if (pb < 320) {                    // W2 rows 0..255 -> [n][256]
            int i2 = (pb - 192) * 256 + threadIdx.x;
            int k = i2 >> 7, n = i2 & 127;
            g_W2h[n * K2 + k] = __float2half_rn(W2[k * DD + n]);
        } else {                                  // cvec
            __shared__ float cb[DD];
            int c = threadIdx.x;
            if (c < DD) cb[c] = fast_cos(fabsf(tb[c]));
            __syncthreads();
            if (c < DD) {
                float a = b2[c];
                for (int d = 0; d < DD; ++d)
                    a = fmaf(cb[d], W2[(size_t)(2 * DD + d) * DD + c], a);
                g_cv[c] = a;
            }
        }
        return;
    }

    const int lane = threadIdx.x & 31, wid = threadIdx.x >> 5;
    const int n = blk * 8 + wid;                  // 3750 * 8 = 30000 exactly

    const ulonglong2 tw2 = *(const ulonglong2*)(tw + lane * 4);
    const ulonglong2 tb2 = *(const ulonglong2*)(tb + lane * 4);
    const u64 INVPI2  = pack2(0.31830988618379067f);
    const u64 MAGIC2  = pack2(12582912.0f);
    const u64 NMAGIC2 = pack2(-12582912.0f);
    const u64 P1N2 = pack2(-3.140625f);
    const u64 P2N2 = pack2(-9.67502593994140625e-4f);
    const u64 P3N2 = pack2(-1.5099579909783764e-7f);

    int nbv = 0, eiv = 0; float etv = 0.f;
    if (lane < KNBR) {
        nbv = nbrs[n * KNBR + lane];
        eiv = eidx[n * KNBR + lane];
        etv = etim[n * KNBR + lane];
    }
    const float tsn = ts[n];

    u64 an0 = 0, an1 = 0, at0 = 0, at1 = 0, ae0 = 0, ae1 = 0;
#pragma unroll
    for (int k = 0; k < KNBR; ++k) {
        const int   nb = __shfl_sync(0xffffffffu, nbv, k);
        const int   ei = __shfl_sync(0xffffffffu, eiv, k);
        const float et = __shfl_sync(0xffffffffu, etv, k);
        const ulonglong2 f1 = *(const ulonglong2*)(nf + (size_t)nb * DD + lane * 4);
        const float4 f2f = __ldcs((const float4*)(ef + (size_t)ei * DD + lane * 4));
        const ulonglong2 f2 = *(const ulonglong2*)&f2f;
        an0 = add2(an0, f1.x); an1 = add2(an1, f1.y);
        ae0 = add2(ae0, f2.x); ae1 = add2(ae1, f2.y);
        const u64 dl2 = pack2(tsn - et);
        at0 = add2(at0, cos2(fma2(dl2, tw2.x, tb2.x),
                             INVPI2, MAGIC2, NMAGIC2, P1N2, P2N2, P3N2));
        at1 = add2(at1, cos2(fma2(dl2, tw2.y, tb2.y),
                             INVPI2, MAGIC2, NMAGIC2, P1N2, P2N2, P3N2));
    }

    float4 an, at, ae;
    unpack2(an0, an.x, an.y); unpack2(an1, an.z, an.w);
    unpack2(at0, at.x, at.y); unpack2(at1, at.z, at.w);
    unpack2(ae0, ae.x, ae.y); unpack2(ae1, ae.z, ae.w);
    size_t base = (size_t)n * K1 + lane * 4;
    *(u64*)(g_Ah + base)       = hi4(an);
    *(u64*)(g_Ah + base + 128) = hi4(at);
    *(u64*)(g_Ah + base + 256) = hi4(ae);
}

// ============================ GEMM kernel (128-row tiles, double-buffered) ============================
// smem: SA x2 (32K) | SB x2 (32K) | SH (32K) | cv 512 | b1 512 = 99328 B -> 2 CTAs/SM
#define SA(b)  ((b) * 16384)
#define SBUF(b) (32768 + (b) * 16384)
#define SH     65536
#define SCV    98304
#define SB1    98816
#define SM_TOTAL 99328

__device__ __forceinline__ void stage_f16(u32 tile, const __half* __restrict__ src,
                                          int rowStride, int r0, int k0) {
    const int t = threadIdx.x;
#pragma unroll
    for (int i = 0; i < 4; ++i) {
        const int idx = t + i * 256;        // 1024 16B segments
        const int row = idx >> 3, seg = idx & 7;
        cp16(tile + SWZ(row * 128 + seg * 16),
             src + (size_t)(r0 + row) * rowStride + k0 + seg * 8);
    }
}
__device__ __forceinline__ void stage_nf(char* th, const float* __restrict__ nf,
                                         int n0, int k0) {
    const int t = threadIdx.x;
#pragma unroll
    for (int i = 0; i < 8; ++i) {
        const int idx = t + i * 256;        // 2048 float4
        const int row = idx >> 4, seg = idx & 15;
        const int n = n0 + row;
        float4 v = {0, 0, 0, 0};
        if (n < NN) v = *(const float4*)(nf + (size_t)n * DD + k0 + seg * 4);
        *(u64*)(th + SWZ(row * 128 + seg * 8)) = hi4(v);
    }
}

// one 64-deep K chunk; warp tile 32 rows x 64 cols
__device__ __forceinline__ void mma_chunk(u32 a_b, u32 b_b,
                                          int wm, int wn, int lane,
                                          float (&acc)[2][8][4]) {
    const int g = lane >> 3, r = lane & 7;
#pragma unroll
    for (int ks = 0; ks < 4; ++ks) {
        const int kb = ks * 32;
        u32 a[2][4], bh[4][4];
#pragma unroll
        for (int mi = 0; mi < 2; ++mi) {
            const int row = wm * 32 + mi * 16 + (g & 1) * 8 + r;
            ldsm4(a[mi], a_b + SWZ(row * 128 + kb + (g >> 1) * 16));
        }
#pragma unroll
        for (int gi = 0; gi < 4; ++gi) {
            const int nrow = wn * 64 + gi * 16 + (g >> 1) * 8 + r;
            ldsm4(bh[gi], b_b + SWZ(nrow * 128 + kb + (g & 1) * 16));
        }
#pragma unroll
        for (int mi = 0; mi < 2; ++mi)
#pragma unroll
            for (int nj = 0; nj < 8; ++nj) {
                const int gi = nj >> 1, p = (nj & 1) * 2;
                mma16816(acc[mi][nj], a[mi], bh[gi][p], bh[gi][p + 1]);
            }
    }
}

__global__ void __launch_bounds__(256)
gemm_kernel(const float* __restrict__ nf, const float* __restrict__ b1,
            float* __restrict__ out) {
    extern __shared__ char sm[];
    const u32 smb = smem_u32(sm);
    const int tid = threadIdx.x, lane = tid & 31, wid = tid >> 5;
    const int wm = wid & 3, wn = wid >> 2;        // 4x2 warp grid, 32x64 warp tile
    const int n0 = blockIdx.x * 128;

    if (tid < DD) {
        ((float*)(sm + SCV))[tid] = g_cv[tid];
        ((float*)(sm + SB1))[tid] = b1[tid];
    }

    float acc[2][8][4];
#pragma unroll
    for (int a = 0; a < 2; ++a)
#pragma unroll
        for (int b = 0; b < 8; ++b)
#pragma unroll
            for (int q = 0; q < 4; ++q) acc[a][b][q] = 0.f;

    // ---------------- GEMM1: D = agg @ W1t^T (K=384, 6 chunks, pipelined) ----------------
    stage_f16(smb + SA(0), g_Ah, K1, n0, 0);
    stage_f16(smb + SBUF(0), g_W1h, K1, 0, 0);
    CP_COMMIT();
#pragma unroll 1
    for (int c = 0; c < 6; ++c) {
        const int cb = c & 1;
        if (c < 5) {
            stage_f16(smb + SA(cb ^ 1), g_Ah, K1, n0, (c + 1) * 64);
            stage_f16(smb + SBUF(cb ^ 1), g_W1h, K1, 0, (c + 1) * 64);
            CP_COMMIT();
            CP_WAIT(1);
        } else {
            CP_WAIT(0);
        }
        __syncthreads();
        mma_chunk(smb + SA(cb), smb + SBUF(cb), wm, wn, lane, acc);
        __syncthreads();
    }

    // ---------------- Epilogue 1: H = relu(D + 20*b1) -> SH (fp16) ----------------
    {
        const float* b1s = (const float*)(sm + SB1);
        char* th = sm + SH + wn * 16384;   // chunk index == wn
#pragma unroll
        for (int mi = 0; mi < 2; ++mi)
#pragma unroll
            for (int nj = 0; nj < 8; ++nj) {
                const int col = wn * 64 + nj * 8 + (lane & 3) * 2;
                const float bb0 = b1s[col], bb1 = b1s[col + 1];
                const int cbyte = (col & 63) * 2;
#pragma unroll
                for (int half = 0; half < 2; ++half) {
                    const int row = wm * 32 + mi * 16 + (lane >> 2) + half * 8;
                    float h0 = fmaxf(fmaf(20.f, bb0, acc[mi][nj][half * 2]),     0.f);
                    float h1 = fmaxf(fmaf(20.f, bb1, acc[mi][nj][half * 2 + 1]), 0.f);
                    u32 hp = (u32)__half_as_ushort(__float2half_rn(h0)) |
                             ((u32)__half_as_ushort(__float2half_rn(h1)) << 16);
                    *(u32*)(th + SWZ(row * 128 + cbyte)) = hp;
                }
            }
    }

    // ---------------- GEMM2: D = [H | nf] @ W2t^T + cvec (K=256, 4 chunks) ----------------
    {
        const float* cvs = (const float*)(sm + SCV);
#pragma unroll
        for (int mi = 0; mi < 2; ++mi)
#pragma unroll
            for (int nj = 0; nj < 8; ++nj) {
                const int col = wn * 64 + nj * 8 + (lane & 3) * 2;
                acc[mi][nj][0] = cvs[col];
                acc[mi][nj][1] = cvs[col + 1];
                acc[mi][nj][2] = cvs[col];
                acc[mi][nj][3] = cvs[col + 1];
            }
    }
    stage_f16(smb + SBUF(0), g_W2h, K2, 0, 0);
    CP_COMMIT();
#pragma unroll 1
    for (int c = 0; c < 4; ++c) {
        const int cb = c & 1;
        if (c < 3) {
            stage_f16(smb + SBUF(cb ^ 1), g_W2h, K2, 0, (c + 1) * 64);
            CP_COMMIT();
        }
        if (c >= 2) stage_nf(sm + SA(cb), nf, n0, (c - 2) * 64);
        if (c < 3) CP_WAIT(1); else CP_WAIT(0);
        __syncthreads();
        const u32 a_b = (c < 2) ? (smb + SH + c * 16384) : (smb + SA(cb));
        mma_chunk(a_b, smb + SBUF(cb), wm, wn, lane, acc);
        __syncthreads();
    }

    // ---------------- Epilogue 2: out = D ----------------
#pragma unroll
    for (int mi = 0; mi < 2; ++mi)
#pragma unroll
        for (int nj = 0; nj < 8; ++nj) {
            const int col = wn * 64 + nj * 8 + (lane & 3) * 2;
#pragma unroll
            for (int half = 0; half < 2; ++half) {
                const int n = n0 + wm * 32 + mi * 16 + (lane >> 2) + half * 8;
                if (n < NN) {
                    float2 o = {acc[mi][nj][half * 2], acc[mi][nj][half * 2 + 1]};
                    *(float2*)(out + (size_t)n * DD + col) = o;
                }
            }
        }
}

extern "C" void kernel_launch(void* const* d_in, const int* in_sizes, int n_in,
                              void* d_out, int out_size) {
    const float* node_features = (const float*)d_in[0];
    const float* timestamps    = (const float*)d_in[1];
    const float* edge_features = (const float*)d_in[2];
    const int*   neighbors     = (const int*)d_in[3];
    const int*   edge_idxs     = (const int*)d_in[4];
    const float* edge_times    = (const float*)d_in[5];
    const float* time_w        = (const float*)d_in[6];
    const float* time_b        = (const float*)d_in[7];
    const float* W1            = (const float*)d_in[8];
    const float* b1            = (const float*)d_in[9];
    const float* W2            = (const float*)d_in[10];
    const float* b2            = (const float*)d_in[11];
    float* out = (float*)d_out;

    cudaFuncSetAttribute(gemm_kernel, cudaFuncAttributeMaxDynamicSharedMemorySize, SM_TOTAL);

    agg_kernel<<<AGG_BLKS + 321, 256>>>(node_features, timestamps, edge_features,
                                        neighbors, edge_idxs, edge_times, time_w, time_b,
                                        W1, W2, b2);
    gemm_kernel<<<N_TILES, 256, SM_TOTAL>>>(node_features, b1, out);
}